// round 11
// baseline (speedup 1.0000x reference)
#include <cuda_runtime.h>
#include <cuda_fp16.h>
#include <cstdint>

#define DIM   2048
#define HID   8192
#define BATCH 4096

// ---------------- GEMM tiling ----------------
#define BM 128
#define BN 128
#define BK 64                      // fp16 K elements per stage (4 k16 steps)
#define STAGES 2
#define A_STG (BM * 128)           // 16384 B (128B rows, XOR-swizzled)
#define STG   (3 * A_STG)          // 49152 B : [Ahi | Alo | B]
#define GEMM_SMEM (STAGES * STG)   // 98304 B -> 2 CTAs/SM
#define CHUNKS 3072                // 16B chunks per stage
#define PERSIST_CTAS 296           // 148 SMs x 2 CTAs

// s is scaled by 1/SSCALE before the final GEMM to avoid fp16 overflow
#define SSCALE 64.0f

// ---------------- device scratch ----------------
__device__ __align__(256) __half g_wf [DIM*DIM];
__device__ __align__(256) __half g_wc [DIM*DIM];
__device__ __align__(256) __half g_wg [DIM*DIM];
__device__ __align__(256) __half g_wo [DIM*DIM];
__device__ __align__(256) __half g_wu [HID*DIM];
__device__ __align__(256) __half g_wg2[HID*DIM];
__device__ __align__(256) __half g_wout[DIM*HID];

__device__ __align__(256) __half g_xhi[BATCH*DIM], g_xlo[BATCH*DIM];
__device__ __align__(256) float g_F[BATCH*DIM], g_C[BATCH*DIM], g_G[BATCH*DIM];
__device__ __align__(256) __half g_thi[BATCH*DIM], g_tlo[BATCH*DIM];
__device__ __align__(256) float g_O[BATCH*DIM];
__device__ __align__(256) __half g_ohi[BATCH*DIM], g_olo[BATCH*DIM];
__device__ __align__(256) float g_GG[BATCH*HID], g_U[BATCH*HID];
__device__ __align__(256) __half g_shi[BATCH*HID], g_slo[BATCH*HID];

// ---------------- PTX helpers ----------------
__device__ __forceinline__ uint32_t smem_u32(const void* p) {
    uint32_t a;
    asm("{ .reg .u64 t; cvta.to.shared.u64 t, %1; cvt.u32.u64 %0, t; }" : "=r"(a) : "l"(p));
    return a;
}
__device__ __forceinline__ void cp_async16(uint32_t s, const void* g) {
    asm volatile("cp.async.cg.shared.global [%0], [%1], 16;\n" :: "r"(s), "l"(g) : "memory");
}
__device__ __forceinline__ void cp_commit() {
    asm volatile("cp.async.commit_group;\n" ::: "memory");
}
__device__ __forceinline__ void ldsm_x4(uint32_t* r, uint32_t a) {
    asm volatile("ldmatrix.sync.aligned.m8n8.x4.shared.b16 {%0,%1,%2,%3}, [%4];\n"
                 : "=r"(r[0]), "=r"(r[1]), "=r"(r[2]), "=r"(r[3]) : "r"(a));
}
__device__ __forceinline__ void mma_f16(float* c, const uint32_t* a, const uint32_t* b) {
    asm volatile(
        "mma.sync.aligned.m16n8k16.row.col.f32.f16.f16.f32 "
        "{%0,%1,%2,%3}, {%4,%5,%6,%7}, {%8,%9}, {%0,%1,%2,%3};\n"
        : "+f"(c[0]), "+f"(c[1]), "+f"(c[2]), "+f"(c[3])
        : "r"(a[0]), "r"(a[1]), "r"(a[2]), "r"(a[3]), "r"(b[0]), "r"(b[1]));
}

// swizzled byte offset within a 128B-row buffer: row r, 16B chunk c
__device__ __forceinline__ uint32_t swz(int r, int c) {
    return (uint32_t)(r * 128 + ((c ^ (r & 7)) * 16));
}

// ---------------- elementwise ----------------
__device__ __forceinline__ float sigmoidf_(float v) { return 1.0f / (1.0f + expf(-v)); }

struct TernArgs {
    const float* src[7];
    __half*      dst[7];
};

__global__ void tern_all_kernel(TernArgs args) {
    const int ndd = DIM * DIM / 8;
    const int nhd = HID * DIM / 8;
    long i = (long)blockIdx.x * blockDim.x + threadIdx.x;
    long total = 4L * ndd + 3L * nhd;
    if (i >= total) return;
    int seg; long off;
    if (i < 4L * ndd) { seg = (int)(i / ndd); off = i - (long)seg * ndd; }
    else { long j = i - 4L * ndd; seg = 4 + (int)(j / nhd); off = j - (long)(seg - 4) * nhd; }
    const float4* s = (const float4*)args.src[seg];
    uint4* d = (uint4*)args.dst[seg];
    float4 a = s[2*off], b = s[2*off+1];
    float v[8] = {a.x, a.y, a.z, a.w, b.x, b.y, b.z, b.w};
    union { uint4 u; __half h[8]; } r;
    #pragma unroll
    for (int j = 0; j < 8; j++) {
        float t = (fabsf(v[j]) < 0.33f) ? 0.0f : (v[j] > 0.0f ? 1.0f : -1.0f);
        r.h[j] = __float2half_rn(t);
    }
    d[off] = r.u;
}

__global__ void split_kernel(const float4* __restrict__ v,
                             uint4* __restrict__ hi, uint4* __restrict__ lo, int n8) {
    int i = blockIdx.x * blockDim.x + threadIdx.x;
    if (i >= n8) return;
    float4 a = v[2*i], b = v[2*i+1];
    float x[8] = {a.x, a.y, a.z, a.w, b.x, b.y, b.z, b.w};
    union { uint4 u; __half h[8]; } rh, rl;
    #pragma unroll
    for (int j = 0; j < 8; j++) {
        __half h = __float2half_rn(x[j]);
        rh.h[j] = h;
        rl.h[j] = __float2half_rn(x[j] - __half2float(h));
    }
    hi[i] = rh.u; lo[i] = rl.u;
}

__global__ void mlgru_ew_kernel(int n4) {
    int i = blockIdx.x * blockDim.x + threadIdx.x;
    if (i >= n4) return;
    float4 f4 = ((const float4*)g_F)[i];
    float4 c4 = ((const float4*)g_C)[i];
    float4 g4 = ((const float4*)g_G)[i];
    float fv[4] = {f4.x, f4.y, f4.z, f4.w};
    float cv[4] = {c4.x, c4.y, c4.z, c4.w};
    float gv[4] = {g4.x, g4.y, g4.z, g4.w};
    union { uint2 u; __half h[4]; } rh, rl;
    #pragma unroll
    for (int j = 0; j < 4; j++) {
        float f = sigmoidf_(fv[j]);
        float c = cv[j] * sigmoidf_(cv[j]);
        float g = sigmoidf_(gv[j]);
        float t = g * (1.0f - f) * c;
        __half h = __float2half_rn(t);
        rh.h[j] = h;
        rl.h[j] = __float2half_rn(t - __half2float(h));
    }
    ((uint2*)g_thi)[i] = rh.u;
    ((uint2*)g_tlo)[i] = rl.u;
}

__global__ void glu_ew_kernel(int n4) {
    int i = blockIdx.x * blockDim.x + threadIdx.x;
    if (i >= n4) return;
    float4 gg4 = ((const float4*)g_GG)[i];
    float4 u4  = ((const float4*)g_U)[i];
    float ggv[4] = {gg4.x, gg4.y, gg4.z, gg4.w};
    float uv[4]  = {u4.x, u4.y, u4.z, u4.w};
    union { uint2 u; __half h[4]; } rh, rl;
    #pragma unroll
    for (int j = 0; j < 4; j++) {
        float gg = sigmoidf_(ggv[j]);
        float u  = uv[j] * sigmoidf_(uv[j]);
        float s  = gg * u * (1.0f / SSCALE);
        __half h = __float2half_rn(s);
        rh.h[j] = h;
        rl.h[j] = __float2half_rn(s - __half2float(h));
    }
    ((uint2*)g_shi)[i] = rh.u;
    ((uint2*)g_slo)[i] = rl.u;
}

// ---------------- HMMA GEMM --------------------------------------------------
// out[M,N] = alpha * ((Ahi + Alo)[M,K] @ W[N,K]^T) + bias   (fp32 out)
// Persistent CTAs (grid = min(tiles, 296)), CTA tile 128x128, 256 threads,
// warp tile 32x64, 2 CTAs/SM, XOR-swizzled 128B-row smem, BK=64, 2 stages.
// Per iter: one top sync; the stage refill is issued between the last
// ks ldsm and its MMA block so the MMA burst hides cp.async issue.
__global__ __launch_bounds__(256, 2) void gemm_hmma(
    const __half* __restrict__ Ahi,
    const __half* __restrict__ Alo,
    const __half* __restrict__ W,
    const float* __restrict__ bias,
    float* __restrict__ out,
    int M, int N, int K, float alpha)
{
    extern __shared__ __align__(16) unsigned char smem[];

    const int tid  = threadIdx.x;
    const int lane = tid & 31;
    const int warp = tid >> 5;      // 0..7
    const int wm   = warp & 3;      // M band: 32 rows
    const int wn   = warp >> 2;     // N band: 64 cols
    const int KT   = K / BK;
    const int tilesN = N / BN;
    const int tiles  = (M / BM) * tilesN;

    const int g1 = (lane >> 3) & 1;
    const int g2 = lane >> 4;
    const int r8 = lane & 7;

    for (int tile = blockIdx.x; tile < tiles; tile += gridDim.x) {
        const long bM = (long)(tile / tilesN) * BM;
        const long bN = (long)(tile % tilesN) * BN;

        float acc[2][8][4];
        #pragma unroll
        for (int i = 0; i < 2; i++)
            #pragma unroll
            for (int j = 0; j < 8; j++)
                #pragma unroll
                for (int k = 0; k < 4; k++) acc[i][j][k] = 0.0f;

        auto issue_tile = [&](int it_, int stg_) {
            long kk = (long)it_ * BK;
            unsigned char* s = smem + stg_ * STG;
            #pragma unroll
            for (int c = tid; c < CHUNKS; c += 256) {
                int buf = c >> 10;            // 0 Ahi, 1 Alo, 2 B
                int cc  = c & 1023;
                int row = cc >> 3, ch = cc & 7;
                const __half* g =
                    (buf == 0) ? (Ahi + (bM + row) * (long)K + kk + ch * 8) :
                    (buf == 1) ? (Alo + (bM + row) * (long)K + kk + ch * 8) :
                                 (W   + (bN + row) * (long)K + kk + ch * 8);
                cp_async16(smem_u32(s + buf * A_STG + swz(row, ch)), g);
            }
            cp_commit();
        };

        // all warps done reading previous tile's stages before overwrite
        __syncthreads();
        issue_tile(0, 0);
        if (KT > 1) issue_tile(1, 1);

        for (int it = 0; it < KT; it++) {
            if (it + 1 < KT) asm volatile("cp.async.wait_group 1;\n" ::: "memory");
            else             asm volatile("cp.async.wait_group 0;\n" ::: "memory");
            __syncthreads();

            int stg = it & 1;
            unsigned char* sAh = smem + stg * STG;
            unsigned char* sAl = sAh + A_STG;
            unsigned char* sB  = sAh + 2 * A_STG;

            #pragma unroll
            for (int ks = 0; ks < 4; ks++) {
                int kss = (ks + warp) & 3;    // 4-phase de-phasing
                uint32_t bF[8][2];
                #pragma unroll
                for (int nb = 0; nb < 4; nb++) {
                    int r = wn * 64 + nb * 16 + g2 * 8 + r8;
                    int c = kss * 2 + g1;
                    uint32_t t[4];
                    ldsm_x4(t, smem_u32(sB + swz(r, c)));
                    bF[nb * 2 + 0][0] = t[0]; bF[nb * 2 + 0][1] = t[1];
                    bF[nb * 2 + 1][0] = t[2]; bF[nb * 2 + 1][1] = t[3];
                }
                uint32_t aH[2][4], aL[2][4];
                #pragma unroll
                for (int mi = 0; mi < 2; mi++) {
                    int r = wm * 32 + mi * 16 + g1 * 8 + r8;
                    int c = kss * 2 + g2;
                    ldsm_x4(aH[mi], smem_u32(sAh + swz(r, c)));
                }
                #pragma unroll
                for (int mi = 0; mi < 2; mi++) {
                    int r = wm * 32 + mi * 16 + g1 * 8 + r8;
                    int c = kss * 2 + g2;
                    ldsm_x4(aL[mi], smem_u32(sAl + swz(r, c)));
                }
                if (ks == 3) {
                    // all reads of this stage are issued; refill it while the
                    // final MMA burst below hides cp.async issue + barrier skew
                    __syncthreads();
                    if (it + 2 < KT) issue_tile(it + 2, stg);
                }
                #pragma unroll
                for (int mi = 0; mi < 2; mi++)
                    #pragma unroll
                    for (int nj = 0; nj < 8; nj++)
                        mma_f16(acc[mi][nj], aH[mi], bF[nj]);
                #pragma unroll
                for (int mi = 0; mi < 2; mi++)
                    #pragma unroll
                    for (int nj = 0; nj < 8; nj++)
                        mma_f16(acc[mi][nj], aL[mi], bF[nj]);
            }
        }

        // epilogue: alpha*acc + bias, fp32 store
        const int cg = lane >> 2, tg = lane & 3;
        #pragma unroll
        for (int mi = 0; mi < 2; mi++) {
            #pragma unroll
            for (int nj = 0; nj < 8; nj++) {
                long row = bM + wm * 32 + mi * 16 + cg;
                long col = bN + wn * 64 + nj * 8 + tg * 2;
                float b0 = bias[col], b1 = bias[col + 1];
                float2 v0 = make_float2(fmaf(alpha, acc[mi][nj][0], b0),
                                        fmaf(alpha, acc[mi][nj][1], b1));
                float2 v1 = make_float2(fmaf(alpha, acc[mi][nj][2], b0),
                                        fmaf(alpha, acc[mi][nj][3], b1));
                *reinterpret_cast<float2*>(out + row * (long)N + col)       = v0;
                *reinterpret_cast<float2*>(out + (row + 8) * (long)N + col) = v1;
            }
        }
    }
}

// ---------------- host launcher ----------------
extern "C" void kernel_launch(void* const* d_in, const int* in_sizes, int n_in,
                              void* d_out, int out_size)
{
    (void)in_sizes; (void)n_in; (void)out_size;
    const float* x    = (const float*)d_in[0];
    const float* wf   = (const float*)d_in[1];
    const float* bf_  = (const float*)d_in[2];
    const float* wc   = (const float*)d_in[3];
    const float* bc   = (const float*)d_in[4];
    const float* wg   = (const float*)d_in[5];
    const float* bg   = (const float*)d_in[6];
    const float* wo   = (const float*)d_in[7];
    const float* bo   = (const float*)d_in[8];
    const float* wu   = (const float*)d_in[9];
    const float* bu   = (const float*)d_in[10];
    const float* wg2  = (const float*)d_in[11];
    const float* bg2  = (const float*)d_in[12];
    const float* wout = (const float*)d_in[13];
    const float* bout = (const float*)d_in[14];
    float* out = (float*)d_out;

    cudaFuncSetAttribute(gemm_hmma, cudaFuncAttributeMaxDynamicSharedMemorySize, GEMM_SMEM);

    void *p_wf, *p_wc, *p_wg, *p_wo, *p_wu, *p_wg2, *p_wout;
    void *p_xhi, *p_xlo, *p_F, *p_C, *p_G, *p_thi, *p_tlo;
    void *p_O, *p_ohi, *p_olo, *p_GG, *p_U, *p_shi, *p_slo;
    cudaGetSymbolAddress(&p_wf, g_wf);     cudaGetSymbolAddress(&p_wc, g_wc);
    cudaGetSymbolAddress(&p_wg, g_wg);     cudaGetSymbolAddress(&p_wo, g_wo);
    cudaGetSymbolAddress(&p_wu, g_wu);     cudaGetSymbolAddress(&p_wg2, g_wg2);
    cudaGetSymbolAddress(&p_wout, g_wout);
    cudaGetSymbolAddress(&p_xhi, g_xhi);   cudaGetSymbolAddress(&p_xlo, g_xlo);
    cudaGetSymbolAddress(&p_F, g_F);       cudaGetSymbolAddress(&p_C, g_C);
    cudaGetSymbolAddress(&p_G, g_G);
    cudaGetSymbolAddress(&p_thi, g_thi);   cudaGetSymbolAddress(&p_tlo, g_tlo);
    cudaGetSymbolAddress(&p_O, g_O);
    cudaGetSymbolAddress(&p_ohi, g_ohi);   cudaGetSymbolAddress(&p_olo, g_olo);
    cudaGetSymbolAddress(&p_GG, g_GG);     cudaGetSymbolAddress(&p_U, g_U);
    cudaGetSymbolAddress(&p_shi, g_shi);   cudaGetSymbolAddress(&p_slo, g_slo);

    const int T = 256;
    const int nBD = BATCH * DIM, nBH = BATCH * HID;

    TernArgs ta;
    ta.src[0] = wf;   ta.dst[0] = (__half*)p_wf;
    ta.src[1] = wc;   ta.dst[1] = (__half*)p_wc;
    ta.src[2] = wg;   ta.dst[2] = (__half*)p_wg;
    ta.src[3] = wo;   ta.dst[3] = (__half*)p_wo;
    ta.src[4] = wu;   ta.dst[4] = (__half*)p_wu;
    ta.src[5] = wg2;  ta.dst[5] = (__half*)p_wg2;
    ta.src[6] = wout; ta.dst[6] = (__half*)p_wout;
    long tern_chunks = 4L * (DIM*DIM/8) + 3L * (HID*DIM/8);
    tern_all_kernel<<<(unsigned)((tern_chunks + T - 1) / T), T>>>(ta);

    split_kernel<<<(nBD/8 + T - 1)/T, T>>>((const float4*)x, (uint4*)p_xhi, (uint4*)p_xlo, nBD/8);

    const int tilesD = (BATCH / BM) * (DIM / BN);   // 512
    const int tilesH = (BATCH / BM) * (HID / BN);   // 2048
    const int gD = tilesD < PERSIST_CTAS ? tilesD : PERSIST_CTAS;
    const int gH = tilesH < PERSIST_CTAS ? tilesH : PERSIST_CTAS;

    gemm_hmma<<<gD, 256, GEMM_SMEM>>>((__half*)p_xhi, (__half*)p_xlo,
                                      (__half*)p_wf, bf_, (float*)p_F, BATCH, DIM, DIM, 1.0f);
    gemm_hmma<<<gD, 256, GEMM_SMEM>>>((__half*)p_xhi, (__half*)p_xlo,
                                      (__half*)p_wc, bc,  (float*)p_C, BATCH, DIM, DIM, 1.0f);
    gemm_hmma<<<gD, 256, GEMM_SMEM>>>((__half*)p_xhi, (__half*)p_xlo,
                                      (__half*)p_wg, bg,  (float*)p_G, BATCH, DIM, DIM, 1.0f);

    mlgru_ew_kernel<<<(nBD/4 + T - 1)/T, T>>>(nBD/4);

    gemm_hmma<<<gD, 256, GEMM_SMEM>>>((__half*)p_thi, (__half*)p_tlo,
                                      (__half*)p_wo, bo, (float*)p_O, BATCH, DIM, DIM, 1.0f);
    split_kernel<<<(nBD/8 + T - 1)/T, T>>>((const float4*)p_O, (uint4*)p_ohi, (uint4*)p_olo, nBD/8);

    gemm_hmma<<<gH, 256, GEMM_SMEM>>>((__half*)p_ohi, (__half*)p_olo,
                                      (__half*)p_wg2, bg2, (float*)p_GG, BATCH, HID, DIM, 1.0f);
    gemm_hmma<<<gH, 256, GEMM_SMEM>>>((__half*)p_ohi, (__half*)p_olo,
                                      (__half*)p_wu,  bu,  (float*)p_U,  BATCH, HID, DIM, 1.0f);

    glu_ew_kernel<<<(nBH/4 + T - 1)/T, T>>>(nBH/4);

    gemm_hmma<<<gD, 256, GEMM_SMEM>>>((__half*)p_shi, (__half*)p_slo,
                                      (__half*)p_wout, bout, out, BATCH, DIM, HID, SSCALE);
}

// round 12
// speedup vs baseline: 1.0056x; 1.0056x over previous
#include <cuda_runtime.h>
#include <cuda_fp16.h>
#include <cstdint>

#define DIM   2048
#define HID   8192
#define BATCH 4096

// ---------------- GEMM tiling ----------------
#define BM 128
#define BN 128
#define BK 64                      // fp16 K elements per stage (4 k16 steps)
#define STAGES 2
#define A_STG (BM * 128)           // 16384 B (128B rows, XOR-swizzled)
#define STG   (3 * A_STG)          // 49152 B : [Ahi | Alo | B]
#define GEMM_SMEM (STAGES * STG)   // 98304 B -> 2 CTAs/SM
#define CHUNKS 3072                // 16B chunks per stage

// s is scaled by 1/SSCALE before the final GEMM to avoid fp16 overflow
#define SSCALE 64.0f

// epilogue modes
#define EPI_F32    0   // out = alpha*acc + bias (fp32)
#define EPI_SPLIT  1   // hi/lo fp16 of (acc + bias)
#define EPI_GLU    2   // s = sig(aux1)*silu(acc+bias)/SSCALE -> hi/lo
#define EPI_MLGRU  3   // t = sig(acc+bias)*(1-sig(aux1))*silu(aux2) -> hi/lo

// ---------------- device scratch ----------------
__device__ __align__(256) __half g_wf [DIM*DIM];
__device__ __align__(256) __half g_wc [DIM*DIM];
__device__ __align__(256) __half g_wg [DIM*DIM];
__device__ __align__(256) __half g_wo [DIM*DIM];
__device__ __align__(256) __half g_wu [HID*DIM];
__device__ __align__(256) __half g_wg2[HID*DIM];
__device__ __align__(256) __half g_wout[DIM*HID];

__device__ __align__(256) __half g_xhi[BATCH*DIM], g_xlo[BATCH*DIM];
__device__ __align__(256) float g_F[BATCH*DIM], g_C[BATCH*DIM];
__device__ __align__(256) __half g_thi[BATCH*DIM], g_tlo[BATCH*DIM];
__device__ __align__(256) __half g_ohi[BATCH*DIM], g_olo[BATCH*DIM];
__device__ __align__(256) float g_GG[BATCH*HID];
__device__ __align__(256) __half g_shi[BATCH*HID], g_slo[BATCH*HID];

// ---------------- PTX helpers ----------------
__device__ __forceinline__ uint32_t smem_u32(const void* p) {
    uint32_t a;
    asm("{ .reg .u64 t; cvta.to.shared.u64 t, %1; cvt.u32.u64 %0, t; }" : "=r"(a) : "l"(p));
    return a;
}
__device__ __forceinline__ void cp_async16(uint32_t s, const void* g) {
    asm volatile("cp.async.cg.shared.global [%0], [%1], 16;\n" :: "r"(s), "l"(g) : "memory");
}
__device__ __forceinline__ void cp_commit() {
    asm volatile("cp.async.commit_group;\n" ::: "memory");
}
__device__ __forceinline__ void ldsm_x4(uint32_t* r, uint32_t a) {
    asm volatile("ldmatrix.sync.aligned.m8n8.x4.shared.b16 {%0,%1,%2,%3}, [%4];\n"
                 : "=r"(r[0]), "=r"(r[1]), "=r"(r[2]), "=r"(r[3]) : "r"(a));
}
__device__ __forceinline__ void mma_f16(float* c, const uint32_t* a, const uint32_t* b) {
    asm volatile(
        "mma.sync.aligned.m16n8k16.row.col.f32.f16.f16.f32 "
        "{%0,%1,%2,%3}, {%4,%5,%6,%7}, {%8,%9}, {%0,%1,%2,%3};\n"
        : "+f"(c[0]), "+f"(c[1]), "+f"(c[2]), "+f"(c[3])
        : "r"(a[0]), "r"(a[1]), "r"(a[2]), "r"(a[3]), "r"(b[0]), "r"(b[1]));
}

// swizzled byte offset within a 128B-row buffer: row r, 16B chunk c
__device__ __forceinline__ uint32_t swz(int r, int c) {
    return (uint32_t)(r * 128 + ((c ^ (r & 7)) * 16));
}

__device__ __forceinline__ float sigmoidf_(float v) { return 1.0f / (1.0f + expf(-v)); }

// ---------------- elementwise ----------------
struct TernArgs {
    const float* src[7];
    __half*      dst[7];
};

__global__ void tern_all_kernel(TernArgs args) {
    const int ndd = DIM * DIM / 8;
    const int nhd = HID * DIM / 8;
    long i = (long)blockIdx.x * blockDim.x + threadIdx.x;
    long total = 4L * ndd + 3L * nhd;
    if (i >= total) return;
    int seg; long off;
    if (i < 4L * ndd) { seg = (int)(i / ndd); off = i - (long)seg * ndd; }
    else { long j = i - 4L * ndd; seg = 4 + (int)(j / nhd); off = j - (long)(seg - 4) * nhd; }
    const float4* s = (const float4*)args.src[seg];
    uint4* d = (uint4*)args.dst[seg];
    float4 a = s[2*off], b = s[2*off+1];
    float v[8] = {a.x, a.y, a.z, a.w, b.x, b.y, b.z, b.w};
    union { uint4 u; __half h[8]; } r;
    #pragma unroll
    for (int j = 0; j < 8; j++) {
        float t = (fabsf(v[j]) < 0.33f) ? 0.0f : (v[j] > 0.0f ? 1.0f : -1.0f);
        r.h[j] = __float2half_rn(t);
    }
    d[off] = r.u;
}

__global__ void split_kernel(const float4* __restrict__ v,
                             uint4* __restrict__ hi, uint4* __restrict__ lo, int n8) {
    int i = blockIdx.x * blockDim.x + threadIdx.x;
    if (i >= n8) return;
    float4 a = v[2*i], b = v[2*i+1];
    float x[8] = {a.x, a.y, a.z, a.w, b.x, b.y, b.z, b.w};
    union { uint4 u; __half h[8]; } rh, rl;
    #pragma unroll
    for (int j = 0; j < 8; j++) {
        __half h = __float2half_rn(x[j]);
        rh.h[j] = h;
        rl.h[j] = __float2half_rn(x[j] - __half2float(h));
    }
    hi[i] = rh.u; lo[i] = rl.u;
}

// ---------------- HMMA GEMM + fused epilogues --------------------------------
// acc = (Ahi + Alo)[M,K] @ W[N,K]^T ; then per-mode epilogue (see EPI_*).
// CTA 128x128, 256 threads, warp tile 32x64, 2 CTAs/SM, XOR-swizzled smem.
__global__ __launch_bounds__(256, 2) void gemm_hmma(
    const __half* __restrict__ Ahi,
    const __half* __restrict__ Alo,
    const __half* __restrict__ W,
    const float* __restrict__ bias,
    float* __restrict__ outF,
    __half* __restrict__ outHi,
    __half* __restrict__ outLo,
    const float* __restrict__ aux1,
    const float* __restrict__ aux2,
    int M, int N, int K, float alpha, int mode)
{
    extern __shared__ __align__(16) unsigned char smem[];

    const int tid  = threadIdx.x;
    const int lane = tid & 31;
    const int warp = tid >> 5;      // 0..7
    const int wm   = warp & 3;      // M band: 32 rows
    const int wn   = warp >> 2;     // N band: 64 cols
    const long bM  = (long)blockIdx.y * BM;
    const long bN  = (long)blockIdx.x * BN;

    const int KT = K / BK;

    float acc[2][8][4];
    #pragma unroll
    for (int i = 0; i < 2; i++)
        #pragma unroll
        for (int j = 0; j < 8; j++)
            #pragma unroll
            for (int k = 0; k < 4; k++) acc[i][j][k] = 0.0f;

    auto issue_tile = [&](int it_, int stg_) {
        long kk = (long)it_ * BK;
        unsigned char* s = smem + stg_ * STG;
        #pragma unroll
        for (int c = tid; c < CHUNKS; c += 256) {
            int buf = c >> 10;            // 0 Ahi, 1 Alo, 2 B
            int cc  = c & 1023;
            int row = cc >> 3, ch = cc & 7;
            const __half* g =
                (buf == 0) ? (Ahi + (bM + row) * (long)K + kk + ch * 8) :
                (buf == 1) ? (Alo + (bM + row) * (long)K + kk + ch * 8) :
                             (W   + (bN + row) * (long)K + kk + ch * 8);
            cp_async16(smem_u32(s + buf * A_STG + swz(row, ch)), g);
        }
        cp_commit();
    };

    issue_tile(0, 0);
    if (KT > 1) issue_tile(1, 1);

    const int g1 = (lane >> 3) & 1;
    const int g2 = lane >> 4;
    const int r8 = lane & 7;
    const int par = warp & 1;       // ks stagger

    for (int it = 0; it < KT; it++) {
        if (it + 1 < KT) asm volatile("cp.async.wait_group 1;\n" ::: "memory");
        else             asm volatile("cp.async.wait_group 0;\n" ::: "memory");
        __syncthreads();

        int stg = it & 1;
        unsigned char* sAh = smem + stg * STG;
        unsigned char* sAl = sAh + A_STG;
        unsigned char* sB  = sAh + 2 * A_STG;

        #pragma unroll
        for (int ks = 0; ks < 4; ks++) {
            int kss = ks ^ par;
            uint32_t bF[8][2];
            #pragma unroll
            for (int nb = 0; nb < 4; nb++) {
                int r = wn * 64 + nb * 16 + g2 * 8 + r8;
                int c = kss * 2 + g1;
                uint32_t t[4];
                ldsm_x4(t, smem_u32(sB + swz(r, c)));
                bF[nb * 2 + 0][0] = t[0]; bF[nb * 2 + 0][1] = t[1];
                bF[nb * 2 + 1][0] = t[2]; bF[nb * 2 + 1][1] = t[3];
            }
            uint32_t aH[2][4], aL[2][4];
            #pragma unroll
            for (int mi = 0; mi < 2; mi++) {
                int r = wm * 32 + mi * 16 + g1 * 8 + r8;
                int c = kss * 2 + g2;
                ldsm_x4(aH[mi], smem_u32(sAh + swz(r, c)));
            }
            #pragma unroll
            for (int mi = 0; mi < 2; mi++) {
                int r = wm * 32 + mi * 16 + g1 * 8 + r8;
                int c = kss * 2 + g2;
                ldsm_x4(aL[mi], smem_u32(sAl + swz(r, c)));
            }
            #pragma unroll
            for (int mi = 0; mi < 2; mi++)
                #pragma unroll
                for (int nj = 0; nj < 8; nj++)
                    mma_f16(acc[mi][nj], aH[mi], bF[nj]);
            #pragma unroll
            for (int mi = 0; mi < 2; mi++)
                #pragma unroll
                for (int nj = 0; nj < 8; nj++)
                    mma_f16(acc[mi][nj], aL[mi], bF[nj]);
        }

        __syncthreads();
        if (it + 2 < KT) issue_tile(it + 2, stg);
    }

    // ---------------- fused epilogue ----------------
    const int cg = lane >> 2, tg = lane & 3;
    #pragma unroll
    for (int mi = 0; mi < 2; mi++) {
        #pragma unroll
        for (int nj = 0; nj < 8; nj++) {
            long row = bM + wm * 32 + mi * 16 + cg;
            long col = bN + wn * 64 + nj * 8 + tg * 2;
            float b0 = bias[col], b1 = bias[col + 1];
            float v[4];
            v[0] = fmaf(alpha, acc[mi][nj][0], b0);
            v[1] = fmaf(alpha, acc[mi][nj][1], b1);
            v[2] = fmaf(alpha, acc[mi][nj][2], b0);
            v[3] = fmaf(alpha, acc[mi][nj][3], b1);
            long i0 = row * (long)N + col;
            long i1 = (row + 8) * (long)N + col;

            if (mode == EPI_F32) {
                *reinterpret_cast<float2*>(outF + i0) = make_float2(v[0], v[1]);
                *reinterpret_cast<float2*>(outF + i1) = make_float2(v[2], v[3]);
            } else {
                if (mode == EPI_GLU) {
                    float gA = sigmoidf_(aux1[i0]), gB = sigmoidf_(aux1[i0 + 1]);
                    float gC = sigmoidf_(aux1[i1]), gD = sigmoidf_(aux1[i1 + 1]);
                    v[0] = gA * (v[0] * sigmoidf_(v[0])) * (1.0f / SSCALE);
                    v[1] = gB * (v[1] * sigmoidf_(v[1])) * (1.0f / SSCALE);
                    v[2] = gC * (v[2] * sigmoidf_(v[2])) * (1.0f / SSCALE);
                    v[3] = gD * (v[3] * sigmoidf_(v[3])) * (1.0f / SSCALE);
                } else if (mode == EPI_MLGRU) {
                    float f0 = sigmoidf_(aux1[i0]), f1 = sigmoidf_(aux1[i0 + 1]);
                    float f2 = sigmoidf_(aux1[i1]), f3 = sigmoidf_(aux1[i1 + 1]);
                    float c0 = aux2[i0],     c1 = aux2[i0 + 1];
                    float c2 = aux2[i1],     c3 = aux2[i1 + 1];
                    c0 *= sigmoidf_(c0); c1 *= sigmoidf_(c1);
                    c2 *= sigmoidf_(c2); c3 *= sigmoidf_(c3);
                    v[0] = sigmoidf_(v[0]) * (1.0f - f0) * c0;
                    v[1] = sigmoidf_(v[1]) * (1.0f - f1) * c1;
                    v[2] = sigmoidf_(v[2]) * (1.0f - f2) * c2;
                    v[3] = sigmoidf_(v[3]) * (1.0f - f3) * c3;
                }
                __half h0 = __float2half_rn(v[0]), h1 = __float2half_rn(v[1]);
                __half h2 = __float2half_rn(v[2]), h3 = __float2half_rn(v[3]);
                __half l0 = __float2half_rn(v[0] - __half2float(h0));
                __half l1 = __float2half_rn(v[1] - __half2float(h1));
                __half l2 = __float2half_rn(v[2] - __half2float(h2));
                __half l3 = __float2half_rn(v[3] - __half2float(h3));
                *reinterpret_cast<__half2*>(outHi + i0) = __halves2half2(h0, h1);
                *reinterpret_cast<__half2*>(outHi + i1) = __halves2half2(h2, h3);
                *reinterpret_cast<__half2*>(outLo + i0) = __halves2half2(l0, l1);
                *reinterpret_cast<__half2*>(outLo + i1) = __halves2half2(l2, l3);
            }
        }
    }
}

// ---------------- host launcher ----------------
extern "C" void kernel_launch(void* const* d_in, const int* in_sizes, int n_in,
                              void* d_out, int out_size)
{
    (void)in_sizes; (void)n_in; (void)out_size;
    const float* x    = (const float*)d_in[0];
    const float* wf   = (const float*)d_in[1];
    const float* bf_  = (const float*)d_in[2];
    const float* wc   = (const float*)d_in[3];
    const float* bc   = (const float*)d_in[4];
    const float* wg   = (const float*)d_in[5];
    const float* bg   = (const float*)d_in[6];
    const float* wo   = (const float*)d_in[7];
    const float* bo   = (const float*)d_in[8];
    const float* wu   = (const float*)d_in[9];
    const float* bu   = (const float*)d_in[10];
    const float* wg2  = (const float*)d_in[11];
    const float* bg2  = (const float*)d_in[12];
    const float* wout = (const float*)d_in[13];
    const float* bout = (const float*)d_in[14];
    float* out = (float*)d_out;

    cudaFuncSetAttribute(gemm_hmma, cudaFuncAttributeMaxDynamicSharedMemorySize, GEMM_SMEM);

    void *p_wf, *p_wc, *p_wg, *p_wo, *p_wu, *p_wg2, *p_wout;
    void *p_xhi, *p_xlo, *p_F, *p_C, *p_thi, *p_tlo;
    void *p_ohi, *p_olo, *p_GG, *p_shi, *p_slo;
    cudaGetSymbolAddress(&p_wf, g_wf);     cudaGetSymbolAddress(&p_wc, g_wc);
    cudaGetSymbolAddress(&p_wg, g_wg);     cudaGetSymbolAddress(&p_wo, g_wo);
    cudaGetSymbolAddress(&p_wu, g_wu);     cudaGetSymbolAddress(&p_wg2, g_wg2);
    cudaGetSymbolAddress(&p_wout, g_wout);
    cudaGetSymbolAddress(&p_xhi, g_xhi);   cudaGetSymbolAddress(&p_xlo, g_xlo);
    cudaGetSymbolAddress(&p_F, g_F);       cudaGetSymbolAddress(&p_C, g_C);
    cudaGetSymbolAddress(&p_thi, g_thi);   cudaGetSymbolAddress(&p_tlo, g_tlo);
    cudaGetSymbolAddress(&p_ohi, g_ohi);   cudaGetSymbolAddress(&p_olo, g_olo);
    cudaGetSymbolAddress(&p_GG, g_GG);
    cudaGetSymbolAddress(&p_shi, g_shi);   cudaGetSymbolAddress(&p_slo, g_slo);

    const int T = 256;
    const int nBD = BATCH * DIM;

    TernArgs ta;
    ta.src[0] = wf;   ta.dst[0] = (__half*)p_wf;
    ta.src[1] = wc;   ta.dst[1] = (__half*)p_wc;
    ta.src[2] = wg;   ta.dst[2] = (__half*)p_wg;
    ta.src[3] = wo;   ta.dst[3] = (__half*)p_wo;
    ta.src[4] = wu;   ta.dst[4] = (__half*)p_wu;
    ta.src[5] = wg2;  ta.dst[5] = (__half*)p_wg2;
    ta.src[6] = wout; ta.dst[6] = (__half*)p_wout;
    long tern_chunks = 4L * (DIM*DIM/8) + 3L * (HID*DIM/8);
    tern_all_kernel<<<(unsigned)((tern_chunks + T - 1) / T), T>>>(ta);

    split_kernel<<<(nBD/8 + T - 1)/T, T>>>((const float4*)x, (uint4*)p_xhi, (uint4*)p_xlo, nBD/8);

    dim3 gridD(DIM / BN, BATCH / BM);   // (16, 32)
    dim3 gridH(HID / BN, BATCH / BM);   // (64, 32)

    // F = x@Wf^T+bf  (fp32)
    gemm_hmma<<<gridD, 256, GEMM_SMEM>>>((__half*)p_xhi, (__half*)p_xlo, (__half*)p_wf, bf_,
                                         (float*)p_F, nullptr, nullptr, nullptr, nullptr,
                                         BATCH, DIM, DIM, 1.0f, EPI_F32);
    // C = x@Wc^T+bc  (fp32)
    gemm_hmma<<<gridD, 256, GEMM_SMEM>>>((__half*)p_xhi, (__half*)p_xlo, (__half*)p_wc, bc,
                                         (float*)p_C, nullptr, nullptr, nullptr, nullptr,
                                         BATCH, DIM, DIM, 1.0f, EPI_F32);
    // t = sig(G)*(1-sig(F))*silu(C) -> thi/tlo   (G computed here)
    gemm_hmma<<<gridD, 256, GEMM_SMEM>>>((__half*)p_xhi, (__half*)p_xlo, (__half*)p_wg, bg,
                                         nullptr, (__half*)p_thi, (__half*)p_tlo,
                                         (const float*)p_F, (const float*)p_C,
                                         BATCH, DIM, DIM, 1.0f, EPI_MLGRU);
    // o = t@Wo^T+bo -> ohi/olo
    gemm_hmma<<<gridD, 256, GEMM_SMEM>>>((__half*)p_thi, (__half*)p_tlo, (__half*)p_wo, bo,
                                         nullptr, (__half*)p_ohi, (__half*)p_olo, nullptr, nullptr,
                                         BATCH, DIM, DIM, 1.0f, EPI_SPLIT);
    // GG = o@Wg2^T+bg2  (fp32)
    gemm_hmma<<<gridH, 256, GEMM_SMEM>>>((__half*)p_ohi, (__half*)p_olo, (__half*)p_wg2, bg2,
                                         (float*)p_GG, nullptr, nullptr, nullptr, nullptr,
                                         BATCH, HID, DIM, 1.0f, EPI_F32);
    // s = sig(GG)*silu(U)/SSCALE -> shi/slo   (U computed here)
    gemm_hmma<<<gridH, 256, GEMM_SMEM>>>((__half*)p_ohi, (__half*)p_olo, (__half*)p_wu, bu,
                                         nullptr, (__half*)p_shi, (__half*)p_slo,
                                         (const float*)p_GG, nullptr,
                                         BATCH, HID, DIM, 1.0f, EPI_GLU);
    // out = SSCALE * (s @ Wout^T) + bout  (fp32)
    gemm_hmma<<<gridD, 256, GEMM_SMEM>>>((__half*)p_shi, (__half*)p_slo, (__half*)p_wout, bout,
                                         out, nullptr, nullptr, nullptr, nullptr,
                                         BATCH, DIM, HID, SSCALE, EPI_F32);
}

// round 13
// speedup vs baseline: 1.0316x; 1.0259x over previous
#include <cuda_runtime.h>
#include <cuda_fp16.h>
#include <cstdint>

#define DIM   2048
#define HID   8192
#define BATCH 4096

// ---------------- GEMM tiling ----------------
#define BM 128
#define BN 128
#define BK 64                      // fp16 K elements per stage (4 k16 steps)
#define STAGES 2
#define A_STG (BM * 128)           // 16384 B (128B rows, XOR-swizzled)
#define STG   (3 * A_STG)          // 49152 B : [Ahi | Alo | B]
#define GEMM_SMEM (STAGES * STG)   // 98304 B -> 2 CTAs/SM
#define CHUNKS 3072                // 16B chunks per stage

// s is scaled by 1/SSCALE before the final GEMM to avoid fp16 overflow
#define SSCALE 64.0f

// ---------------- device scratch ----------------
__device__ __align__(256) __half g_wf [DIM*DIM];
__device__ __align__(256) __half g_wc [DIM*DIM];
__device__ __align__(256) __half g_wg [DIM*DIM];
__device__ __align__(256) __half g_wo [DIM*DIM];
__device__ __align__(256) __half g_wu [HID*DIM];
__device__ __align__(256) __half g_wg2[HID*DIM];
__device__ __align__(256) __half g_wout[DIM*HID];

__device__ __align__(256) __half g_xhi[BATCH*DIM], g_xlo[BATCH*DIM];
__device__ __align__(256) float g_F[BATCH*DIM], g_C[BATCH*DIM], g_G[BATCH*DIM];
__device__ __align__(256) __half g_thi[BATCH*DIM], g_tlo[BATCH*DIM];
__device__ __align__(256) float g_O[BATCH*DIM];
__device__ __align__(256) __half g_ohi[BATCH*DIM], g_olo[BATCH*DIM];
__device__ __align__(256) float g_GG[BATCH*HID], g_U[BATCH*HID];
__device__ __align__(256) __half g_shi[BATCH*HID], g_slo[BATCH*HID];

// ---------------- PTX helpers ----------------
__device__ __forceinline__ uint32_t smem_u32(const void* p) {
    uint32_t a;
    asm("{ .reg .u64 t; cvta.to.shared.u64 t, %1; cvt.u32.u64 %0, t; }" : "=r"(a) : "l"(p));
    return a;
}
__device__ __forceinline__ void cp_async16(uint32_t s, const void* g) {
    asm volatile("cp.async.cg.shared.global [%0], [%1], 16;\n" :: "r"(s), "l"(g) : "memory");
}
__device__ __forceinline__ void cp_commit() {
    asm volatile("cp.async.commit_group;\n" ::: "memory");
}
__device__ __forceinline__ void ldsm_x4(uint32_t* r, uint32_t a) {
    asm volatile("ldmatrix.sync.aligned.m8n8.x4.shared.b16 {%0,%1,%2,%3}, [%4];\n"
                 : "=r"(r[0]), "=r"(r[1]), "=r"(r[2]), "=r"(r[3]) : "r"(a));
}
__device__ __forceinline__ void mma_f16(float* c, const uint32_t* a, const uint32_t* b) {
    asm volatile(
        "mma.sync.aligned.m16n8k16.row.col.f32.f16.f16.f32 "
        "{%0,%1,%2,%3}, {%4,%5,%6,%7}, {%8,%9}, {%0,%1,%2,%3};\n"
        : "+f"(c[0]), "+f"(c[1]), "+f"(c[2]), "+f"(c[3])
        : "r"(a[0]), "r"(a[1]), "r"(a[2]), "r"(a[3]), "r"(b[0]), "r"(b[1]));
}

// swizzled byte offset within a 128B-row buffer: row r, 16B chunk c
__device__ __forceinline__ uint32_t swz(int r, int c) {
    return (uint32_t)(r * 128 + ((c ^ (r & 7)) * 16));
}

__device__ __forceinline__ float sigmoidf_(float v) { return 1.0f / (1.0f + expf(-v)); }

// ---------------- elementwise ----------------
struct TernArgs {
    const float* src[7];
    __half*      dst[7];
};

__global__ void tern_all_kernel(TernArgs args) {
    const int ndd = DIM * DIM / 8;
    const int nhd = HID * DIM / 8;
    long i = (long)blockIdx.x * blockDim.x + threadIdx.x;
    long total = 4L * ndd + 3L * nhd;
    if (i >= total) return;
    int seg; long off;
    if (i < 4L * ndd) { seg = (int)(i / ndd); off = i - (long)seg * ndd; }
    else { long j = i - 4L * ndd; seg = 4 + (int)(j / nhd); off = j - (long)(seg - 4) * nhd; }
    const float4* s = (const float4*)args.src[seg];
    uint4* d = (uint4*)args.dst[seg];
    float4 a = s[2*off], b = s[2*off+1];
    float v[8] = {a.x, a.y, a.z, a.w, b.x, b.y, b.z, b.w};
    union { uint4 u; __half h[8]; } r;
    #pragma unroll
    for (int j = 0; j < 8; j++) {
        float t = (fabsf(v[j]) < 0.33f) ? 0.0f : (v[j] > 0.0f ? 1.0f : -1.0f);
        r.h[j] = __float2half_rn(t);
    }
    d[off] = r.u;
}

__global__ void split_kernel(const float4* __restrict__ v,
                             uint4* __restrict__ hi, uint4* __restrict__ lo, int n8) {
    int i = blockIdx.x * blockDim.x + threadIdx.x;
    if (i >= n8) return;
    float4 a = v[2*i], b = v[2*i+1];
    float x[8] = {a.x, a.y, a.z, a.w, b.x, b.y, b.z, b.w};
    union { uint4 u; __half h[8]; } rh, rl;
    #pragma unroll
    for (int j = 0; j < 8; j++) {
        __half h = __float2half_rn(x[j]);
        rh.h[j] = h;
        rl.h[j] = __float2half_rn(x[j] - __half2float(h));
    }
    hi[i] = rh.u; lo[i] = rl.u;
}

__global__ void mlgru_ew_kernel(int n4) {
    int i = blockIdx.x * blockDim.x + threadIdx.x;
    if (i >= n4) return;
    float4 f4 = ((const float4*)g_F)[i];
    float4 c4 = ((const float4*)g_C)[i];
    float4 g4 = ((const float4*)g_G)[i];
    float fv[4] = {f4.x, f4.y, f4.z, f4.w};
    float cv[4] = {c4.x, c4.y, c4.z, c4.w};
    float gv[4] = {g4.x, g4.y, g4.z, g4.w};
    union { uint2 u; __half h[4]; } rh, rl;
    #pragma unroll
    for (int j = 0; j < 4; j++) {
        float f = sigmoidf_(fv[j]);
        float c = cv[j] * sigmoidf_(cv[j]);
        float g = sigmoidf_(gv[j]);
        float t = g * (1.0f - f) * c;
        __half h = __float2half_rn(t);
        rh.h[j] = h;
        rl.h[j] = __float2half_rn(t - __half2float(h));
    }
    ((uint2*)g_thi)[i] = rh.u;
    ((uint2*)g_tlo)[i] = rl.u;
}

__global__ void glu_ew_kernel(int n4) {
    int i = blockIdx.x * blockDim.x + threadIdx.x;
    if (i >= n4) return;
    float4 gg4 = ((const float4*)g_GG)[i];
    float4 u4  = ((const float4*)g_U)[i];
    float ggv[4] = {gg4.x, gg4.y, gg4.z, gg4.w};
    float uv[4]  = {u4.x, u4.y, u4.z, u4.w};
    union { uint2 u; __half h[4]; } rh, rl;
    #pragma unroll
    for (int j = 0; j < 4; j++) {
        float gg = sigmoidf_(ggv[j]);
        float u  = uv[j] * sigmoidf_(uv[j]);
        float s  = gg * u * (1.0f / SSCALE);
        __half h = __float2half_rn(s);
        rh.h[j] = h;
        rl.h[j] = __float2half_rn(s - __half2float(h));
    }
    ((uint2*)g_shi)[i] = rh.u;
    ((uint2*)g_slo)[i] = rl.u;
}

// ---------------- HMMA GEMM (z-batched) --------------------------------------
// For z in grid.z: out[z][M,N] = alpha*((Ahi+Alo)[M,K] @ W[z][N,K]^T) + bias[z].
// A shared across z (L2 reuse). CTA 128x128, 256 threads, warp tile 32x64,
// 2 CTAs/SM, XOR-swizzled 128B-row smem, BK=64, 2 stages. (R10 mainloop.)
struct GemmArgs {
    const __half* Ahi;
    const __half* Alo;
    const __half* W[3];
    const float*  bias[3];
    float*        out[3];
    int M, N, K;
    float alpha;
};

__global__ __launch_bounds__(256, 2) void gemm_hmma(GemmArgs a)
{
    extern __shared__ __align__(16) unsigned char smem[];

    const int tid  = threadIdx.x;
    const int lane = tid & 31;
    const int warp = tid >> 5;      // 0..7
    const int wm   = warp & 3;      // M band: 32 rows
    const int wn   = warp >> 2;     // N band: 64 cols
    const long bM  = (long)blockIdx.y * BM;
    const long bN  = (long)blockIdx.x * BN;
    const int  z   = blockIdx.z;

    const __half* __restrict__ Ahi = a.Ahi;
    const __half* __restrict__ Alo = a.Alo;
    const __half* __restrict__ W    = a.W[z];
    const float*  __restrict__ bias = a.bias[z];
    float*        __restrict__ out  = a.out[z];
    const int N = a.N, K = a.K;
    const float alpha = a.alpha;

    const int KT = K / BK;

    float acc[2][8][4];
    #pragma unroll
    for (int i = 0; i < 2; i++)
        #pragma unroll
        for (int j = 0; j < 8; j++)
            #pragma unroll
            for (int k = 0; k < 4; k++) acc[i][j][k] = 0.0f;

    auto issue_tile = [&](int it_, int stg_) {
        long kk = (long)it_ * BK;
        unsigned char* s = smem + stg_ * STG;
        #pragma unroll
        for (int c = tid; c < CHUNKS; c += 256) {
            int buf = c >> 10;            // 0 Ahi, 1 Alo, 2 B
            int cc  = c & 1023;
            int row = cc >> 3, ch = cc & 7;
            const __half* g =
                (buf == 0) ? (Ahi + (bM + row) * (long)K + kk + ch * 8) :
                (buf == 1) ? (Alo + (bM + row) * (long)K + kk + ch * 8) :
                             (W   + (bN + row) * (long)K + kk + ch * 8);
            cp_async16(smem_u32(s + buf * A_STG + swz(row, ch)), g);
        }
        cp_commit();
    };

    issue_tile(0, 0);
    if (KT > 1) issue_tile(1, 1);

    const int g1 = (lane >> 3) & 1;
    const int g2 = lane >> 4;
    const int r8 = lane & 7;
    const int par = warp & 1;       // ks stagger

    for (int it = 0; it < KT; it++) {
        if (it + 1 < KT) asm volatile("cp.async.wait_group 1;\n" ::: "memory");
        else             asm volatile("cp.async.wait_group 0;\n" ::: "memory");
        __syncthreads();

        int stg = it & 1;
        unsigned char* sAh = smem + stg * STG;
        unsigned char* sAl = sAh + A_STG;
        unsigned char* sB  = sAh + 2 * A_STG;

        #pragma unroll
        for (int ks = 0; ks < 4; ks++) {
            int kss = ks ^ par;
            uint32_t bF[8][2];
            #pragma unroll
            for (int nb = 0; nb < 4; nb++) {
                int r = wn * 64 + nb * 16 + g2 * 8 + r8;
                int c = kss * 2 + g1;
                uint32_t t[4];
                ldsm_x4(t, smem_u32(sB + swz(r, c)));
                bF[nb * 2 + 0][0] = t[0]; bF[nb * 2 + 0][1] = t[1];
                bF[nb * 2 + 1][0] = t[2]; bF[nb * 2 + 1][1] = t[3];
            }
            uint32_t aH[2][4], aL[2][4];
            #pragma unroll
            for (int mi = 0; mi < 2; mi++) {
                int r = wm * 32 + mi * 16 + g1 * 8 + r8;
                int c = kss * 2 + g2;
                ldsm_x4(aH[mi], smem_u32(sAh + swz(r, c)));
            }
            #pragma unroll
            for (int mi = 0; mi < 2; mi++) {
                int r = wm * 32 + mi * 16 + g1 * 8 + r8;
                int c = kss * 2 + g2;
                ldsm_x4(aL[mi], smem_u32(sAl + swz(r, c)));
            }
            #pragma unroll
            for (int mi = 0; mi < 2; mi++)
                #pragma unroll
                for (int nj = 0; nj < 8; nj++)
                    mma_f16(acc[mi][nj], aH[mi], bF[nj]);
            #pragma unroll
            for (int mi = 0; mi < 2; mi++)
                #pragma unroll
                for (int nj = 0; nj < 8; nj++)
                    mma_f16(acc[mi][nj], aL[mi], bF[nj]);
        }

        __syncthreads();
        if (it + 2 < KT) issue_tile(it + 2, stg);
    }

    // epilogue: alpha*acc + bias, fp32 store
    const int cg = lane >> 2, tg = lane & 3;
    #pragma unroll
    for (int mi = 0; mi < 2; mi++) {
        #pragma unroll
        for (int nj = 0; nj < 8; nj++) {
            long row = bM + wm * 32 + mi * 16 + cg;
            long col = bN + wn * 64 + nj * 8 + tg * 2;
            float b0 = bias[col], b1 = bias[col + 1];
            float2 v0 = make_float2(fmaf(alpha, acc[mi][nj][0], b0),
                                    fmaf(alpha, acc[mi][nj][1], b1));
            float2 v1 = make_float2(fmaf(alpha, acc[mi][nj][2], b0),
                                    fmaf(alpha, acc[mi][nj][3], b1));
            *reinterpret_cast<float2*>(out + row * (long)N + col)       = v0;
            *reinterpret_cast<float2*>(out + (row + 8) * (long)N + col) = v1;
        }
    }
}

// ---------------- host launcher ----------------
extern "C" void kernel_launch(void* const* d_in, const int* in_sizes, int n_in,
                              void* d_out, int out_size)
{
    (void)in_sizes; (void)n_in; (void)out_size;
    const float* x    = (const float*)d_in[0];
    const float* wf   = (const float*)d_in[1];
    const float* bf_  = (const float*)d_in[2];
    const float* wc   = (const float*)d_in[3];
    const float* bc   = (const float*)d_in[4];
    const float* wg   = (const float*)d_in[5];
    const float* bg   = (const float*)d_in[6];
    const float* wo   = (const float*)d_in[7];
    const float* bo   = (const float*)d_in[8];
    const float* wu   = (const float*)d_in[9];
    const float* bu   = (const float*)d_in[10];
    const float* wg2  = (const float*)d_in[11];
    const float* bg2  = (const float*)d_in[12];
    const float* wout = (const float*)d_in[13];
    const float* bout = (const float*)d_in[14];
    float* out = (float*)d_out;

    cudaFuncSetAttribute(gemm_hmma, cudaFuncAttributeMaxDynamicSharedMemorySize, GEMM_SMEM);

    void *p_wf, *p_wc, *p_wg, *p_wo, *p_wu, *p_wg2, *p_wout;
    void *p_xhi, *p_xlo, *p_F, *p_C, *p_G, *p_thi, *p_tlo;
    void *p_O, *p_ohi, *p_olo, *p_GG, *p_U, *p_shi, *p_slo;
    cudaGetSymbolAddress(&p_wf, g_wf);     cudaGetSymbolAddress(&p_wc, g_wc);
    cudaGetSymbolAddress(&p_wg, g_wg);     cudaGetSymbolAddress(&p_wo, g_wo);
    cudaGetSymbolAddress(&p_wu, g_wu);     cudaGetSymbolAddress(&p_wg2, g_wg2);
    cudaGetSymbolAddress(&p_wout, g_wout);
    cudaGetSymbolAddress(&p_xhi, g_xhi);   cudaGetSymbolAddress(&p_xlo, g_xlo);
    cudaGetSymbolAddress(&p_F, g_F);       cudaGetSymbolAddress(&p_C, g_C);
    cudaGetSymbolAddress(&p_G, g_G);
    cudaGetSymbolAddress(&p_thi, g_thi);   cudaGetSymbolAddress(&p_tlo, g_tlo);
    cudaGetSymbolAddress(&p_O, g_O);
    cudaGetSymbolAddress(&p_ohi, g_ohi);   cudaGetSymbolAddress(&p_olo, g_olo);
    cudaGetSymbolAddress(&p_GG, g_GG);     cudaGetSymbolAddress(&p_U, g_U);
    cudaGetSymbolAddress(&p_shi, g_shi);   cudaGetSymbolAddress(&p_slo, g_slo);

    const int T = 256;
    const int nBD = BATCH * DIM, nBH = BATCH * HID;

    TernArgs ta;
    ta.src[0] = wf;   ta.dst[0] = (__half*)p_wf;
    ta.src[1] = wc;   ta.dst[1] = (__half*)p_wc;
    ta.src[2] = wg;   ta.dst[2] = (__half*)p_wg;
    ta.src[3] = wo;   ta.dst[3] = (__half*)p_wo;
    ta.src[4] = wu;   ta.dst[4] = (__half*)p_wu;
    ta.src[5] = wg2;  ta.dst[5] = (__half*)p_wg2;
    ta.src[6] = wout; ta.dst[6] = (__half*)p_wout;
    long tern_chunks = 4L * (DIM*DIM/8) + 3L * (HID*DIM/8);
    tern_all_kernel<<<(unsigned)((tern_chunks + T - 1) / T), T>>>(ta);

    split_kernel<<<(nBD/8 + T - 1)/T, T>>>((const float4*)x, (uint4*)p_xhi, (uint4*)p_xlo, nBD/8);

    // ---- F, C, G in one z-batched launch (shared A; 1536 CTAs) ----
    {
        GemmArgs ga;
        ga.Ahi = (__half*)p_xhi; ga.Alo = (__half*)p_xlo;
        ga.W[0] = (__half*)p_wf; ga.bias[0] = bf_; ga.out[0] = (float*)p_F;
        ga.W[1] = (__half*)p_wc; ga.bias[1] = bc;  ga.out[1] = (float*)p_C;
        ga.W[2] = (__half*)p_wg; ga.bias[2] = bg;  ga.out[2] = (float*)p_G;
        ga.M = BATCH; ga.N = DIM; ga.K = DIM; ga.alpha = 1.0f;
        dim3 grid(DIM / BN, BATCH / BM, 3);
        gemm_hmma<<<grid, 256, GEMM_SMEM>>>(ga);
    }

    mlgru_ew_kernel<<<(nBD/4 + T - 1)/T, T>>>(nBD/4);

    // ---- O = t @ Wo^T + bo ----
    {
        GemmArgs ga;
        ga.Ahi = (__half*)p_thi; ga.Alo = (__half*)p_tlo;
        ga.W[0] = (__half*)p_wo; ga.bias[0] = bo; ga.out[0] = (float*)p_O;
        ga.W[1] = ga.W[0]; ga.bias[1] = ga.bias[0]; ga.out[1] = ga.out[0];
        ga.W[2] = ga.W[0]; ga.bias[2] = ga.bias[0]; ga.out[2] = ga.out[0];
        ga.M = BATCH; ga.N = DIM; ga.K = DIM; ga.alpha = 1.0f;
        dim3 grid(DIM / BN, BATCH / BM, 1);
        gemm_hmma<<<grid, 256, GEMM_SMEM>>>(ga);
    }

    split_kernel<<<(nBD/8 + T - 1)/T, T>>>((const float4*)p_O, (uint4*)p_ohi, (uint4*)p_olo, nBD/8);

    // ---- GG, U in one z-batched launch (shared A; 4096 CTAs) ----
    {
        GemmArgs ga;
        ga.Ahi = (__half*)p_ohi; ga.Alo = (__half*)p_olo;
        ga.W[0] = (__half*)p_wg2; ga.bias[0] = bg2; ga.out[0] = (float*)p_GG;
        ga.W[1] = (__half*)p_wu;  ga.bias[1] = bu;  ga.out[1] = (float*)p_U;
        ga.W[2] = ga.W[0]; ga.bias[2] = ga.bias[0]; ga.out[2] = ga.out[0];
        ga.M = BATCH; ga.N = HID; ga.K = DIM; ga.alpha = 1.0f;
        dim3 grid(HID / BN, BATCH / BM, 2);
        gemm_hmma<<<grid, 256, GEMM_SMEM>>>(ga);
    }

    glu_ew_kernel<<<(nBH/4 + T - 1)/T, T>>>(nBH/4);

    // ---- out = SSCALE * (s @ Wout^T) + bout ----
    {
        GemmArgs ga;
        ga.Ahi = (__half*)p_shi; ga.Alo = (__half*)p_slo;
        ga.W[0] = (__half*)p_wout; ga.bias[0] = bout; ga.out[0] = out;
        ga.W[1] = ga.W[0]; ga.bias[1] = ga.bias[0]; ga.out[1] = ga.out[0];
        ga.W[2] = ga.W[0]; ga.bias[2] = ga.bias[0]; ga.out[2] = ga.out[0];
        ga.M = BATCH; ga.N = DIM; ga.K = HID; ga.alpha = SSCALE;
        dim3 grid(DIM / BN, BATCH / BM, 1);
        gemm_hmma<<<grid, 256, GEMM_SMEM>>>(ga);
    }
}

// round 15
// speedup vs baseline: 1.0572x; 1.0248x over previous
#include <cuda_runtime.h>
#include <cuda_fp16.h>
#include <cstdint>

#define DIM   2048
#define HID   8192
#define BATCH 4096

// ---------------- GEMM tiling ----------------
#define BM 128
#define BN 128
#define BK 64                      // fp16 K elements per half-stage (4 k16 steps)
#define A_STG (BM * 128)           // 16384 B (128B rows, XOR-swizzled)
#define STG   (3 * A_STG)          // 49152 B : [Ahi | Alo | B] per half-stage
#define NSTG 2                     // two half-stages processed per barrier pair
#define GEMM_SMEM (NSTG * STG)     // 98304 B -> 2 CTAs/SM
#define CHUNKS 3072                // 16B chunks per half-stage: 1024 per buffer

// s is scaled by 1/SSCALE before the final GEMM to avoid fp16 overflow
#define SSCALE 64.0f

// ---------------- device scratch ----------------
__device__ __align__(256) __half g_wf [DIM*DIM];
__device__ __align__(256) __half g_wc [DIM*DIM];
__device__ __align__(256) __half g_wg [DIM*DIM];
__device__ __align__(256) __half g_wo [DIM*DIM];
__device__ __align__(256) __half g_wu [HID*DIM];
__device__ __align__(256) __half g_wg2[HID*DIM];
__device__ __align__(256) __half g_wout[DIM*HID];

__device__ __align__(256) __half g_xhi[BATCH*DIM], g_xlo[BATCH*DIM];
__device__ __align__(256) float g_F[BATCH*DIM], g_C[BATCH*DIM], g_G[BATCH*DIM];
__device__ __align__(256) __half g_thi[BATCH*DIM], g_tlo[BATCH*DIM];
__device__ __align__(256) float g_O[BATCH*DIM];
__device__ __align__(256) __half g_ohi[BATCH*DIM], g_olo[BATCH*DIM];
__device__ __align__(256) float g_GG[BATCH*HID], g_U[BATCH*HID];
__device__ __align__(256) __half g_shi[BATCH*HID], g_slo[BATCH*HID];

// ---------------- PTX helpers ----------------
__device__ __forceinline__ uint32_t smem_u32(const void* p) {
    uint32_t a;
    asm("{ .reg .u64 t; cvta.to.shared.u64 t, %1; cvt.u32.u64 %0, t; }" : "=r"(a) : "l"(p));
    return a;
}
__device__ __forceinline__ void cp_async16(uint32_t s, const void* g) {
    asm volatile("cp.async.cg.shared.global [%0], [%1], 16;\n" :: "r"(s), "l"(g) : "memory");
}
__device__ __forceinline__ void cp_commit() {
    asm volatile("cp.async.commit_group;\n" ::: "memory");
}
__device__ __forceinline__ void ldsm_x4(uint32_t* r, uint32_t a) {
    asm volatile("ldmatrix.sync.aligned.m8n8.x4.shared.b16 {%0,%1,%2,%3}, [%4];\n"
                 : "=r"(r[0]), "=r"(r[1]), "=r"(r[2]), "=r"(r[3]) : "r"(a));
}
__device__ __forceinline__ void mma_f16(float* c, const uint32_t* a, const uint32_t* b) {
    asm volatile(
        "mma.sync.aligned.m16n8k16.row.col.f32.f16.f16.f32 "
        "{%0,%1,%2,%3}, {%4,%5,%6,%7}, {%8,%9}, {%0,%1,%2,%3};\n"
        : "+f"(c[0]), "+f"(c[1]), "+f"(c[2]), "+f"(c[3])
        : "r"(a[0]), "r"(a[1]), "r"(a[2]), "r"(a[3]), "r"(b[0]), "r"(b[1]));
}

// swizzled byte offset within a 128B-row buffer: row r, 16B chunk c
__device__ __forceinline__ uint32_t swz(int r, int c) {
    return (uint32_t)(r * 128 + ((c ^ (r & 7)) * 16));
}

__device__ __forceinline__ float sigmoidf_(float v) { return 1.0f / (1.0f + expf(-v)); }

// ---------------- elementwise ----------------
struct TernArgs {
    const float* src[7];
    __half*      dst[7];
};

__global__ void tern_all_kernel(TernArgs args) {
    const int ndd = DIM * DIM / 8;
    const int nhd = HID * DIM / 8;
    long i = (long)blockIdx.x * blockDim.x + threadIdx.x;
    long total = 4L * ndd + 3L * nhd;
    if (i >= total) return;
    int seg; long off;
    if (i < 4L * ndd) { seg = (int)(i / ndd); off = i - (long)seg * ndd; }
    else { long j = i - 4L * ndd; seg = 4 + (int)(j / nhd); off = j - (long)(seg - 4) * nhd; }
    const float4* s = (const float4*)args.src[seg];
    uint4* d = (uint4*)args.dst[seg];
    float4 a = s[2*off], b = s[2*off+1];
    float v[8] = {a.x, a.y, a.z, a.w, b.x, b.y, b.z, b.w};
    union { uint4 u; __half h[8]; } r;
    #pragma unroll
    for (int j = 0; j < 8; j++) {
        float t = (fabsf(v[j]) < 0.33f) ? 0.0f : (v[j] > 0.0f ? 1.0f : -1.0f);
        r.h[j] = __float2half_rn(t);
    }
    d[off] = r.u;
}

__global__ void split_kernel(const float4* __restrict__ v,
                             uint4* __restrict__ hi, uint4* __restrict__ lo, int n8) {
    int i = blockIdx.x * blockDim.x + threadIdx.x;
    if (i >= n8) return;
    float4 a = v[2*i], b = v[2*i+1];
    float x[8] = {a.x, a.y, a.z, a.w, b.x, b.y, b.z, b.w};
    union { uint4 u; __half h[8]; } rh, rl;
    #pragma unroll
    for (int j = 0; j < 8; j++) {
        __half h = __float2half_rn(x[j]);
        rh.h[j] = h;
        rl.h[j] = __float2half_rn(x[j] - __half2float(h));
    }
    hi[i] = rh.u; lo[i] = rl.u;
}

__global__ void mlgru_ew_kernel(int n4) {
    int i = blockIdx.x * blockDim.x + threadIdx.x;
    if (i >= n4) return;
    float4 f4 = ((const float4*)g_F)[i];
    float4 c4 = ((const float4*)g_C)[i];
    float4 g4 = ((const float4*)g_G)[i];
    float fv[4] = {f4.x, f4.y, f4.z, f4.w};
    float cv[4] = {c4.x, c4.y, c4.z, c4.w};
    float gv[4] = {g4.x, g4.y, g4.z, g4.w};
    union { uint2 u; __half h[4]; } rh, rl;
    #pragma unroll
    for (int j = 0; j < 4; j++) {
        float f = sigmoidf_(fv[j]);
        float c = cv[j] * sigmoidf_(cv[j]);
        float g = sigmoidf_(gv[j]);
        float t = g * (1.0f - f) * c;
        __half h = __float2half_rn(t);
        rh.h[j] = h;
        rl.h[j] = __float2half_rn(t - __half2float(h));
    }
    ((uint2*)g_thi)[i] = rh.u;
    ((uint2*)g_tlo)[i] = rl.u;
}

__global__ void glu_ew_kernel(int n4) {
    int i = blockIdx.x * blockDim.x + threadIdx.x;
    if (i >= n4) return;
    float4 gg4 = ((const float4*)g_GG)[i];
    float4 u4  = ((const float4*)g_U)[i];
    float ggv[4] = {gg4.x, gg4.y, gg4.z, gg4.w};
    float uv[4]  = {u4.x, u4.y, u4.z, u4.w};
    union { uint2 u; __half h[4]; } rh, rl;
    #pragma unroll
    for (int j = 0; j < 4; j++) {
        float gg = sigmoidf_(ggv[j]);
        float u  = uv[j] * sigmoidf_(uv[j]);
        float s  = gg * u * (1.0f / SSCALE);
        __half h = __float2half_rn(s);
        rh.h[j] = h;
        rl.h[j] = __float2half_rn(s - __half2float(h));
    }
    ((uint2*)g_shi)[i] = rh.u;
    ((uint2*)g_slo)[i] = rl.u;
}

// ---------------- HMMA GEMM --------------------------------------------------
// out[M,N] = alpha * ((Ahi + Alo)[M,K] @ W[N,K]^T) + bias   (fp32 out)
// CTA 128x128, 256 threads, warp tile 32x64, 2 CTAs/SM, XOR-swizzled smem.
// Two BK=64 half-stages per barrier pair (128 K-elems between barriers):
// wait all -> sync -> compute 8 ks across both halves -> sync -> refill both.
// Half the barrier crossings of R10; cross-CTA overlap hides the load latency.
__global__ __launch_bounds__(256, 2) void gemm_hmma(
    const __half* __restrict__ Ahi,
    const __half* __restrict__ Alo,
    const __half* __restrict__ W,
    const float* __restrict__ bias,
    float* __restrict__ out,
    int M, int N, int K, float alpha)
{
    extern __shared__ __align__(16) unsigned char smem[];

    const int tid  = threadIdx.x;
    const int lane = tid & 31;
    const int warp = tid >> 5;      // 0..7
    const int wm   = warp & 3;      // M band: 32 rows
    const int wn   = warp >> 2;     // N band: 64 cols
    const long bM  = (long)blockIdx.y * BM;
    const long bN  = (long)blockIdx.x * BN;

    const int KI = K / (2 * BK);    // iterations, 128 K-elems each

    float acc[2][8][4];
    #pragma unroll
    for (int i = 0; i < 2; i++)
        #pragma unroll
        for (int j = 0; j < 8; j++)
            #pragma unroll
            for (int k = 0; k < 4; k++) acc[i][j][k] = 0.0f;

    // fill one BK=64 half-stage (hs = 0 or 1) of iteration it_
    // CHUNKS = 3072: chunks [0,1024) Ahi, [1024,2048) Alo, [2048,3072) B.
    auto issue_half = [&](int it_, int hs) {
        long kk = (long)it_ * (2 * BK) + (long)hs * BK;
        unsigned char* s = smem + hs * STG;
        #pragma unroll
        for (int c = tid; c < CHUNKS; c += 256) {
            int buf = c >> 10;            // 0 Ahi, 1 Alo, 2 B
            int cc  = c & 1023;
            int row = cc >> 3, ch = cc & 7;
            const __half* g =
                (buf == 0) ? (Ahi + (bM + row) * (long)K + kk + ch * 8) :
                (buf == 1) ? (Alo + (bM + row) * (long)K + kk + ch * 8) :
                             (W   + (bN + row) * (long)K + kk + ch * 8);
            cp_async16(smem_u32(s + buf * A_STG + swz(row, ch)), g);
        }
        cp_commit();
    };

    issue_half(0, 0);
    issue_half(0, 1);

    const int g1 = (lane >> 3) & 1;
    const int g2 = lane >> 4;
    const int r8 = lane & 7;
    const int par = warp & 1;       // ks stagger

    for (int it = 0; it < KI; it++) {
        asm volatile("cp.async.wait_group 0;\n" ::: "memory");
        __syncthreads();

        #pragma unroll
        for (int hs = 0; hs < 2; hs++) {
            unsigned char* sAh = smem + hs * STG;
            unsigned char* sAl = sAh + A_STG;
            unsigned char* sB  = sAh + 2 * A_STG;

            #pragma unroll
            for (int ks = 0; ks < 4; ks++) {
                int kss = ks ^ par;
                uint32_t bF[8][2];
                #pragma unroll
                for (int nb = 0; nb < 4; nb++) {
                    int r = wn * 64 + nb * 16 + g2 * 8 + r8;
                    int c = kss * 2 + g1;
                    uint32_t t[4];
                    ldsm_x4(t, smem_u32(sB + swz(r, c)));
                    bF[nb * 2 + 0][0] = t[0]; bF[nb * 2 + 0][1] = t[1];
                    bF[nb * 2 + 1][0] = t[2]; bF[nb * 2 + 1][1] = t[3];
                }
                uint32_t aH[2][4], aL[2][4];
                #pragma unroll
                for (int mi = 0; mi < 2; mi++) {
                    int r = wm * 32 + mi * 16 + g1 * 8 + r8;
                    int c = kss * 2 + g2;
                    ldsm_x4(aH[mi], smem_u32(sAh + swz(r, c)));
                }
                #pragma unroll
                for (int mi = 0; mi < 2; mi++) {
                    int r = wm * 32 + mi * 16 + g1 * 8 + r8;
                    int c = kss * 2 + g2;
                    ldsm_x4(aL[mi], smem_u32(sAl + swz(r, c)));
                }
                #pragma unroll
                for (int mi = 0; mi < 2; mi++)
                    #pragma unroll
                    for (int nj = 0; nj < 8; nj++)
                        mma_f16(acc[mi][nj], aH[mi], bF[nj]);
                #pragma unroll
                for (int mi = 0; mi < 2; mi++)
                    #pragma unroll
                    for (int nj = 0; nj < 8; nj++)
                        mma_f16(acc[mi][nj], aL[mi], bF[nj]);
            }
        }

        __syncthreads();
        if (it + 1 < KI) {
            issue_half(it + 1, 0);
            issue_half(it + 1, 1);
        }
    }

    // epilogue: alpha*acc + bias, fp32 store
    const int cg = lane >> 2, tg = lane & 3;
    #pragma unroll
    for (int mi = 0; mi < 2; mi++) {
        #pragma unroll
        for (int nj = 0; nj < 8; nj++) {
            long row = bM + wm * 32 + mi * 16 + cg;
            long col = bN + wn * 64 + nj * 8 + tg * 2;
            float b0 = bias[col], b1 = bias[col + 1];
            float2 v0 = make_float2(fmaf(alpha, acc[mi][nj][0], b0),
                                    fmaf(alpha, acc[mi][nj][1], b1));
            float2 v1 = make_float2(fmaf(alpha, acc[mi][nj][2], b0),
                                    fmaf(alpha, acc[mi][nj][3], b1));
            *reinterpret_cast<float2*>(out + row * (long)N + col)       = v0;
            *reinterpret_cast<float2*>(out + (row + 8) * (long)N + col) = v1;
        }
    }
}

// ---------------- host launcher ----------------
extern "C" void kernel_launch(void* const* d_in, const int* in_sizes, int n_in,
                              void* d_out, int out_size)
{
    (void)in_sizes; (void)n_in; (void)out_size;
    const float* x    = (const float*)d_in[0];
    const float* wf   = (const float*)d_in[1];
    const float* bf_  = (const float*)d_in[2];
    const float* wc   = (const float*)d_in[3];
    const float* bc   = (const float*)d_in[4];
    const float* wg   = (const float*)d_in[5];
    const float* bg   = (const float*)d_in[6];
    const float* wo   = (const float*)d_in[7];
    const float* bo   = (const float*)d_in[8];
    const float* wu   = (const float*)d_in[9];
    const float* bu   = (const float*)d_in[10];
    const float* wg2  = (const float*)d_in[11];
    const float* bg2  = (const float*)d_in[12];
    const float* wout = (const float*)d_in[13];
    const float* bout = (const float*)d_in[14];
    float* out = (float*)d_out;

    cudaFuncSetAttribute(gemm_hmma, cudaFuncAttributeMaxDynamicSharedMemorySize, GEMM_SMEM);

    void *p_wf, *p_wc, *p_wg, *p_wo, *p_wu, *p_wg2, *p_wout;
    void *p_xhi, *p_xlo, *p_F, *p_C, *p_G, *p_thi, *p_tlo;
    void *p_O, *p_ohi, *p_olo, *p_GG, *p_U, *p_shi, *p_slo;
    cudaGetSymbolAddress(&p_wf, g_wf);     cudaGetSymbolAddress(&p_wc, g_wc);
    cudaGetSymbolAddress(&p_wg, g_wg);     cudaGetSymbolAddress(&p_wo, g_wo);
    cudaGetSymbolAddress(&p_wu, g_wu);     cudaGetSymbolAddress(&p_wg2, g_wg2);
    cudaGetSymbolAddress(&p_wout, g_wout);
    cudaGetSymbolAddress(&p_xhi, g_xhi);   cudaGetSymbolAddress(&p_xlo, g_xlo);
    cudaGetSymbolAddress(&p_F, g_F);       cudaGetSymbolAddress(&p_C, g_C);
    cudaGetSymbolAddress(&p_G, g_G);
    cudaGetSymbolAddress(&p_thi, g_thi);   cudaGetSymbolAddress(&p_tlo, g_tlo);
    cudaGetSymbolAddress(&p_O, g_O);
    cudaGetSymbolAddress(&p_ohi, g_ohi);   cudaGetSymbolAddress(&p_olo, g_olo);
    cudaGetSymbolAddress(&p_GG, g_GG);     cudaGetSymbolAddress(&p_U, g_U);
    cudaGetSymbolAddress(&p_shi, g_shi);   cudaGetSymbolAddress(&p_slo, g_slo);

    const int T = 256;
    const int nBD = BATCH * DIM, nBH = BATCH * HID;

    TernArgs ta;
    ta.src[0] = wf;   ta.dst[0] = (__half*)p_wf;
    ta.src[1] = wc;   ta.dst[1] = (__half*)p_wc;
    ta.src[2] = wg;   ta.dst[2] = (__half*)p_wg;
    ta.src[3] = wo;   ta.dst[3] = (__half*)p_wo;
    ta.src[4] = wu;   ta.dst[4] = (__half*)p_wu;
    ta.src[5] = wg2;  ta.dst[5] = (__half*)p_wg2;
    ta.src[6] = wout; ta.dst[6] = (__half*)p_wout;
    long tern_chunks = 4L * (DIM*DIM/8) + 3L * (HID*DIM/8);
    tern_all_kernel<<<(unsigned)((tern_chunks + T - 1) / T), T>>>(ta);

    split_kernel<<<(nBD/8 + T - 1)/T, T>>>((const float4*)x, (uint4*)p_xhi, (uint4*)p_xlo, nBD/8);

    dim3 gridD(DIM / BN, BATCH / BM);   // (16, 32)
    dim3 gridH(HID / BN, BATCH / BM);   // (64, 32)

    gemm_hmma<<<gridD, 256, GEMM_SMEM>>>((__half*)p_xhi, (__half*)p_xlo,
                                         (__half*)p_wf, bf_, (float*)p_F, BATCH, DIM, DIM, 1.0f);
    gemm_hmma<<<gridD, 256, GEMM_SMEM>>>((__half*)p_xhi, (__half*)p_xlo,
                                         (__half*)p_wc, bc,  (float*)p_C, BATCH, DIM, DIM, 1.0f);
    gemm_hmma<<<gridD, 256, GEMM_SMEM>>>((__half*)p_xhi, (__half*)p_xlo,
                                         (__half*)p_wg, bg,  (float*)p_G, BATCH, DIM, DIM, 1.0f);

    mlgru_ew_kernel<<<(nBD/4 + T - 1)/T, T>>>(nBD/4);

    gemm_hmma<<<gridD, 256, GEMM_SMEM>>>((__half*)p_thi, (__half*)p_tlo,
                                         (__half*)p_wo, bo, (float*)p_O, BATCH, DIM, DIM, 1.0f);
    split_kernel<<<(nBD/8 + T - 1)/T, T>>>((const float4*)p_O, (uint4*)p_ohi, (uint4*)p_olo, nBD/8);

    gemm_hmma<<<gridH, 256, GEMM_SMEM>>>((__half*)p_ohi, (__half*)p_olo,
                                         (__half*)p_wg2, bg2, (float*)p_GG, BATCH, HID, DIM, 1.0f);
    gemm_hmma<<<gridH, 256, GEMM_SMEM>>>((__half*)p_ohi, (__half*)p_olo,
                                         (__half*)p_wu,  bu,  (float*)p_U,  BATCH, HID, DIM, 1.0f);

    glu_ew_kernel<<<(nBH/4 + T - 1)/T, T>>>(nBH/4);

    gemm_hmma<<<gridD, 256, GEMM_SMEM>>>((__half*)p_shi, (__half*)p_slo,
                                         (__half*)p_wout, bout, out, BATCH, DIM, HID, SSCALE);
}

// round 16
// speedup vs baseline: 1.1382x; 1.0766x over previous
#include <cuda_runtime.h>
#include <cuda_fp16.h>
#include <cstdint>

#define DIM   2048
#define HID   8192
#define BATCH 4096

// ---------------- GEMM tiling ----------------
#define BM 128
#define BN 128
#define BK 64                      // fp16 K elements per half-stage (4 k16 steps)
#define A_STG (BM * 128)           // 16384 B (128B rows, XOR-swizzled)
#define STG   (3 * A_STG)          // 49152 B : [Ahi | Alo | B] per half-stage
#define NSTG 2                     // two half-stages processed per barrier pair
#define GEMM_SMEM (NSTG * STG)     // 98304 B -> 2 CTAs/SM
#define CHUNKS 3072                // 16B chunks per half-stage: 1024 per buffer

// s is scaled by 1/SSCALE before the final GEMM to avoid fp16 overflow
#define SSCALE 64.0f

// ---------------- device scratch ----------------
__device__ __align__(256) __half g_wf [DIM*DIM];
__device__ __align__(256) __half g_wc [DIM*DIM];
__device__ __align__(256) __half g_wg [DIM*DIM];
__device__ __align__(256) __half g_wo [DIM*DIM];
__device__ __align__(256) __half g_wu [HID*DIM];
__device__ __align__(256) __half g_wg2[HID*DIM];
__device__ __align__(256) __half g_wout[DIM*HID];

__device__ __align__(256) __half g_xhi[BATCH*DIM], g_xlo[BATCH*DIM];
__device__ __align__(256) float g_F[BATCH*DIM], g_C[BATCH*DIM], g_G[BATCH*DIM];
__device__ __align__(256) __half g_thi[BATCH*DIM], g_tlo[BATCH*DIM];
__device__ __align__(256) float g_O[BATCH*DIM];
__device__ __align__(256) __half g_ohi[BATCH*DIM], g_olo[BATCH*DIM];
__device__ __align__(256) float g_GG[BATCH*HID], g_U[BATCH*HID];
__device__ __align__(256) __half g_sh[BATCH*HID];

// ---------------- PTX helpers ----------------
__device__ __forceinline__ uint32_t smem_u32(const void* p) {
    uint32_t a;
    asm("{ .reg .u64 t; cvta.to.shared.u64 t, %1; cvt.u32.u64 %0, t; }" : "=r"(a) : "l"(p));
    return a;
}
__device__ __forceinline__ void cp_async16(uint32_t s, const void* g) {
    asm volatile("cp.async.cg.shared.global [%0], [%1], 16;\n" :: "r"(s), "l"(g) : "memory");
}
__device__ __forceinline__ void cp_commit() {
    asm volatile("cp.async.commit_group;\n" ::: "memory");
}
__device__ __forceinline__ void ldsm_x4(uint32_t* r, uint32_t a) {
    asm volatile("ldmatrix.sync.aligned.m8n8.x4.shared.b16 {%0,%1,%2,%3}, [%4];\n"
                 : "=r"(r[0]), "=r"(r[1]), "=r"(r[2]), "=r"(r[3]) : "r"(a));
}
__device__ __forceinline__ void mma_f16(float* c, const uint32_t* a, const uint32_t* b) {
    asm volatile(
        "mma.sync.aligned.m16n8k16.row.col.f32.f16.f16.f32 "
        "{%0,%1,%2,%3}, {%4,%5,%6,%7}, {%8,%9}, {%0,%1,%2,%3};\n"
        : "+f"(c[0]), "+f"(c[1]), "+f"(c[2]), "+f"(c[3])
        : "r"(a[0]), "r"(a[1]), "r"(a[2]), "r"(a[3]), "r"(b[0]), "r"(b[1]));
}

// swizzled byte offset within a 128B-row buffer: row r, 16B chunk c
__device__ __forceinline__ uint32_t swz(int r, int c) {
    return (uint32_t)(r * 128 + ((c ^ (r & 7)) * 16));
}

__device__ __forceinline__ float sigmoidf_(float v) { return 1.0f / (1.0f + expf(-v)); }

// ---------------- elementwise ----------------
struct TernArgs {
    const float* src[7];
    __half*      dst[7];
};

__global__ void tern_all_kernel(TernArgs args) {
    const int ndd = DIM * DIM / 8;
    const int nhd = HID * DIM / 8;
    long i = (long)blockIdx.x * blockDim.x + threadIdx.x;
    long total = 4L * ndd + 3L * nhd;
    if (i >= total) return;
    int seg; long off;
    if (i < 4L * ndd) { seg = (int)(i / ndd); off = i - (long)seg * ndd; }
    else { long j = i - 4L * ndd; seg = 4 + (int)(j / nhd); off = j - (long)(seg - 4) * nhd; }
    const float4* s = (const float4*)args.src[seg];
    uint4* d = (uint4*)args.dst[seg];
    float4 a = s[2*off], b = s[2*off+1];
    float v[8] = {a.x, a.y, a.z, a.w, b.x, b.y, b.z, b.w};
    union { uint4 u; __half h[8]; } r;
    #pragma unroll
    for (int j = 0; j < 8; j++) {
        float t = (fabsf(v[j]) < 0.33f) ? 0.0f : (v[j] > 0.0f ? 1.0f : -1.0f);
        r.h[j] = __float2half_rn(t);
    }
    d[off] = r.u;
}

__global__ void split_kernel(const float4* __restrict__ v,
                             uint4* __restrict__ hi, uint4* __restrict__ lo, int n8) {
    int i = blockIdx.x * blockDim.x + threadIdx.x;
    if (i >= n8) return;
    float4 a = v[2*i], b = v[2*i+1];
    float x[8] = {a.x, a.y, a.z, a.w, b.x, b.y, b.z, b.w};
    union { uint4 u; __half h[8]; } rh, rl;
    #pragma unroll
    for (int j = 0; j < 8; j++) {
        __half h = __float2half_rn(x[j]);
        rh.h[j] = h;
        rl.h[j] = __float2half_rn(x[j] - __half2float(h));
    }
    hi[i] = rh.u; lo[i] = rl.u;
}

__global__ void mlgru_ew_kernel(int n4) {
    int i = blockIdx.x * blockDim.x + threadIdx.x;
    if (i >= n4) return;
    float4 f4 = ((const float4*)g_F)[i];
    float4 c4 = ((const float4*)g_C)[i];
    float4 g4 = ((const float4*)g_G)[i];
    float fv[4] = {f4.x, f4.y, f4.z, f4.w};
    float cv[4] = {c4.x, c4.y, c4.z, c4.w};
    float gv[4] = {g4.x, g4.y, g4.z, g4.w};
    union { uint2 u; __half h[4]; } rh, rl;
    #pragma unroll
    for (int j = 0; j < 4; j++) {
        float f = sigmoidf_(fv[j]);
        float c = cv[j] * sigmoidf_(cv[j]);
        float g = sigmoidf_(gv[j]);
        float t = g * (1.0f - f) * c;
        __half h = __float2half_rn(t);
        rh.h[j] = h;
        rl.h[j] = __float2half_rn(t - __half2float(h));
    }
    ((uint2*)g_thi)[i] = rh.u;
    ((uint2*)g_tlo)[i] = rl.u;
}

// s = sigmoid(GG)*silu(U) / SSCALE -> single fp16 (no lo: final GEMM is ungated)
__global__ void glu_ew_kernel(int n4) {
    int i = blockIdx.x * blockDim.x + threadIdx.x;
    if (i >= n4) return;
    float4 gg4 = ((const float4*)g_GG)[i];
    float4 u4  = ((const float4*)g_U)[i];
    float ggv[4] = {gg4.x, gg4.y, gg4.z, gg4.w};
    float uv[4]  = {u4.x, u4.y, u4.z, u4.w};
    union { uint2 u; __half h[4]; } rh;
    #pragma unroll
    for (int j = 0; j < 4; j++) {
        float gg = sigmoidf_(ggv[j]);
        float u  = uv[j] * sigmoidf_(uv[j]);
        rh.h[j] = __float2half_rn(gg * u * (1.0f / SSCALE));
    }
    ((uint2*)g_sh)[i] = rh.u;
}

// ---------------- HMMA GEMM --------------------------------------------------
// out[M,N] = alpha * ((Ahi [+ Alo])[M,K] @ W[N,K]^T) + bias   (fp32 out)
// CTA 128x128, 256 threads, warp tile 32x64, 2 CTAs/SM, XOR-swizzled smem.
// Two BK=64 half-stages per barrier pair (128 K-elems between barriers).
// useLo==0 skips the Alo buffer entirely (loads, ldsm and lo-MMAs).
__global__ __launch_bounds__(256, 2) void gemm_hmma(
    const __half* __restrict__ Ahi,
    const __half* __restrict__ Alo,
    const __half* __restrict__ W,
    const float* __restrict__ bias,
    float* __restrict__ out,
    int M, int N, int K, float alpha, int useLo)
{
    extern __shared__ __align__(16) unsigned char smem[];

    const int tid  = threadIdx.x;
    const int lane = tid & 31;
    const int warp = tid >> 5;      // 0..7
    const int wm   = warp & 3;      // M band: 32 rows
    const int wn   = warp >> 2;     // N band: 64 cols
    const long bM  = (long)blockIdx.y * BM;
    const long bN  = (long)blockIdx.x * BN;

    const int KI = K / (2 * BK);    // iterations, 128 K-elems each

    float acc[2][8][4];
    #pragma unroll
    for (int i = 0; i < 2; i++)
        #pragma unroll
        for (int j = 0; j < 8; j++)
            #pragma unroll
            for (int k = 0; k < 4; k++) acc[i][j][k] = 0.0f;

    // fill one BK=64 half-stage (hs = 0 or 1) of iteration it_
    // CHUNKS = 3072: chunks [0,1024) Ahi, [1024,2048) Alo, [2048,3072) B.
    auto issue_half = [&](int it_, int hs) {
        long kk = (long)it_ * (2 * BK) + (long)hs * BK;
        unsigned char* s = smem + hs * STG;
        #pragma unroll
        for (int c = tid; c < CHUNKS; c += 256) {
            int buf = c >> 10;            // 0 Ahi, 1 Alo, 2 B
            if (buf == 1 && !useLo) continue;
            int cc  = c & 1023;
            int row = cc >> 3, ch = cc & 7;
            const __half* g =
                (buf == 0) ? (Ahi + (bM + row) * (long)K + kk + ch * 8) :
                (buf == 1) ? (Alo + (bM + row) * (long)K + kk + ch * 8) :
                             (W   + (bN + row) * (long)K + kk + ch * 8);
            cp_async16(smem_u32(s + buf * A_STG + swz(row, ch)), g);
        }
        cp_commit();
    };

    issue_half(0, 0);
    issue_half(0, 1);

    const int g1 = (lane >> 3) & 1;
    const int g2 = lane >> 4;
    const int r8 = lane & 7;
    const int par = warp & 1;       // ks stagger

    for (int it = 0; it < KI; it++) {
        asm volatile("cp.async.wait_group 0;\n" ::: "memory");
        __syncthreads();

        #pragma unroll
        for (int hs = 0; hs < 2; hs++) {
            unsigned char* sAh = smem + hs * STG;
            unsigned char* sAl = sAh + A_STG;
            unsigned char* sB  = sAh + 2 * A_STG;

            #pragma unroll
            for (int ks = 0; ks < 4; ks++) {
                int kss = ks ^ par;
                uint32_t bF[8][2];
                #pragma unroll
                for (int nb = 0; nb < 4; nb++) {
                    int r = wn * 64 + nb * 16 + g2 * 8 + r8;
                    int c = kss * 2 + g1;
                    uint32_t t[4];
                    ldsm_x4(t, smem_u32(sB + swz(r, c)));
                    bF[nb * 2 + 0][0] = t[0]; bF[nb * 2 + 0][1] = t[1];
                    bF[nb * 2 + 1][0] = t[2]; bF[nb * 2 + 1][1] = t[3];
                }
                uint32_t aH[2][4];
                #pragma unroll
                for (int mi = 0; mi < 2; mi++) {
                    int r = wm * 32 + mi * 16 + g1 * 8 + r8;
                    int c = kss * 2 + g2;
                    ldsm_x4(aH[mi], smem_u32(sAh + swz(r, c)));
                }
                if (useLo) {
                    uint32_t aL[2][4];
                    #pragma unroll
                    for (int mi = 0; mi < 2; mi++) {
                        int r = wm * 32 + mi * 16 + g1 * 8 + r8;
                        int c = kss * 2 + g2;
                        ldsm_x4(aL[mi], smem_u32(sAl + swz(r, c)));
                    }
                    #pragma unroll
                    for (int mi = 0; mi < 2; mi++)
                        #pragma unroll
                        for (int nj = 0; nj < 8; nj++)
                            mma_f16(acc[mi][nj], aH[mi], bF[nj]);
                    #pragma unroll
                    for (int mi = 0; mi < 2; mi++)
                        #pragma unroll
                        for (int nj = 0; nj < 8; nj++)
                            mma_f16(acc[mi][nj], aL[mi], bF[nj]);
                } else {
                    #pragma unroll
                    for (int mi = 0; mi < 2; mi++)
                        #pragma unroll
                        for (int nj = 0; nj < 8; nj++)
                            mma_f16(acc[mi][nj], aH[mi], bF[nj]);
                }
            }
        }

        __syncthreads();
        if (it + 1 < KI) {
            issue_half(it + 1, 0);
            issue_half(it + 1, 1);
        }
    }

    // epilogue: alpha*acc + bias, fp32 store
    const int cg = lane >> 2, tg = lane & 3;
    #pragma unroll
    for (int mi = 0; mi < 2; mi++) {
        #pragma unroll
        for (int nj = 0; nj < 8; nj++) {
            long row = bM + wm * 32 + mi * 16 + cg;
            long col = bN + wn * 64 + nj * 8 + tg * 2;
            float b0 = bias[col], b1 = bias[col + 1];
            float2 v0 = make_float2(fmaf(alpha, acc[mi][nj][0], b0),
                                    fmaf(alpha, acc[mi][nj][1], b1));
            float2 v1 = make_float2(fmaf(alpha, acc[mi][nj][2], b0),
                                    fmaf(alpha, acc[mi][nj][3], b1));
            *reinterpret_cast<float2*>(out + row * (long)N + col)       = v0;
            *reinterpret_cast<float2*>(out + (row + 8) * (long)N + col) = v1;
        }
    }
}

// ---------------- host launcher ----------------
extern "C" void kernel_launch(void* const* d_in, const int* in_sizes, int n_in,
                              void* d_out, int out_size)
{
    (void)in_sizes; (void)n_in; (void)out_size;
    const float* x    = (const float*)d_in[0];
    const float* wf   = (const float*)d_in[1];
    const float* bf_  = (const float*)d_in[2];
    const float* wc   = (const float*)d_in[3];
    const float* bc   = (const float*)d_in[4];
    const float* wg   = (const float*)d_in[5];
    const float* bg   = (const float*)d_in[6];
    const float* wo   = (const float*)d_in[7];
    const float* bo   = (const float*)d_in[8];
    const float* wu   = (const float*)d_in[9];
    const float* bu   = (const float*)d_in[10];
    const float* wg2  = (const float*)d_in[11];
    const float* bg2  = (const float*)d_in[12];
    const float* wout = (const float*)d_in[13];
    const float* bout = (const float*)d_in[14];
    float* out = (float*)d_out;

    cudaFuncSetAttribute(gemm_hmma, cudaFuncAttributeMaxDynamicSharedMemorySize, GEMM_SMEM);

    void *p_wf, *p_wc, *p_wg, *p_wo, *p_wu, *p_wg2, *p_wout;
    void *p_xhi, *p_xlo, *p_F, *p_C, *p_G, *p_thi, *p_tlo;
    void *p_O, *p_ohi, *p_olo, *p_GG, *p_U, *p_sh;
    cudaGetSymbolAddress(&p_wf, g_wf);     cudaGetSymbolAddress(&p_wc, g_wc);
    cudaGetSymbolAddress(&p_wg, g_wg);     cudaGetSymbolAddress(&p_wo, g_wo);
    cudaGetSymbolAddress(&p_wu, g_wu);     cudaGetSymbolAddress(&p_wg2, g_wg2);
    cudaGetSymbolAddress(&p_wout, g_wout);
    cudaGetSymbolAddress(&p_xhi, g_xhi);   cudaGetSymbolAddress(&p_xlo, g_xlo);
    cudaGetSymbolAddress(&p_F, g_F);       cudaGetSymbolAddress(&p_C, g_C);
    cudaGetSymbolAddress(&p_G, g_G);
    cudaGetSymbolAddress(&p_thi, g_thi);   cudaGetSymbolAddress(&p_tlo, g_tlo);
    cudaGetSymbolAddress(&p_O, g_O);
    cudaGetSymbolAddress(&p_ohi, g_ohi);   cudaGetSymbolAddress(&p_olo, g_olo);
    cudaGetSymbolAddress(&p_GG, g_GG);     cudaGetSymbolAddress(&p_U, g_U);
    cudaGetSymbolAddress(&p_sh, g_sh);

    const int T = 256;
    const int nBD = BATCH * DIM, nBH = BATCH * HID;

    TernArgs ta;
    ta.src[0] = wf;   ta.dst[0] = (__half*)p_wf;
    ta.src[1] = wc;   ta.dst[1] = (__half*)p_wc;
    ta.src[2] = wg;   ta.dst[2] = (__half*)p_wg;
    ta.src[3] = wo;   ta.dst[3] = (__half*)p_wo;
    ta.src[4] = wu;   ta.dst[4] = (__half*)p_wu;
    ta.src[5] = wg2;  ta.dst[5] = (__half*)p_wg2;
    ta.src[6] = wout; ta.dst[6] = (__half*)p_wout;
    long tern_chunks = 4L * (DIM*DIM/8) + 3L * (HID*DIM/8);
    tern_all_kernel<<<(unsigned)((tern_chunks + T - 1) / T), T>>>(ta);

    split_kernel<<<(nBD/8 + T - 1)/T, T>>>((const float4*)x, (uint4*)p_xhi, (uint4*)p_xlo, nBD/8);

    dim3 gridD(DIM / BN, BATCH / BM);   // (16, 32)
    dim3 gridH(HID / BN, BATCH / BM);   // (64, 32)

    gemm_hmma<<<gridD, 256, GEMM_SMEM>>>((__half*)p_xhi, (__half*)p_xlo,
                                         (__half*)p_wf, bf_, (float*)p_F, BATCH, DIM, DIM, 1.0f, 1);
    gemm_hmma<<<gridD, 256, GEMM_SMEM>>>((__half*)p_xhi, (__half*)p_xlo,
                                         (__half*)p_wc, bc,  (float*)p_C, BATCH, DIM, DIM, 1.0f, 1);
    gemm_hmma<<<gridD, 256, GEMM_SMEM>>>((__half*)p_xhi, (__half*)p_xlo,
                                         (__half*)p_wg, bg,  (float*)p_G, BATCH, DIM, DIM, 1.0f, 1);

    mlgru_ew_kernel<<<(nBD/4 + T - 1)/T, T>>>(nBD/4);

    gemm_hmma<<<gridD, 256, GEMM_SMEM>>>((__half*)p_thi, (__half*)p_tlo,
                                         (__half*)p_wo, bo, (float*)p_O, BATCH, DIM, DIM, 1.0f, 1);
    split_kernel<<<(nBD/8 + T - 1)/T, T>>>((const float4*)p_O, (uint4*)p_ohi, (uint4*)p_olo, nBD/8);

    gemm_hmma<<<gridH, 256, GEMM_SMEM>>>((__half*)p_ohi, (__half*)p_olo,
                                         (__half*)p_wg2, bg2, (float*)p_GG, BATCH, HID, DIM, 1.0f, 1);
    gemm_hmma<<<gridH, 256, GEMM_SMEM>>>((__half*)p_ohi, (__half*)p_olo,
                                         (__half*)p_wu,  bu,  (float*)p_U,  BATCH, HID, DIM, 1.0f, 1);

    glu_ew_kernel<<<(nBH/4 + T - 1)/T, T>>>(nBH/4);

    // final GEMM: single fp16 A (no gate downstream -> no amplification)
    gemm_hmma<<<gridD, 256, GEMM_SMEM>>>((__half*)p_sh, (__half*)p_sh,
                                         (__half*)p_wout, bout, out, BATCH, DIM, HID, SSCALE, 0);
}

// round 17
// speedup vs baseline: 1.1888x; 1.0445x over previous
#include <cuda_runtime.h>
#include <cuda_fp16.h>
#include <cstdint>

#define DIM   2048
#define HID   8192
#define BATCH 4096

// ---------------- GEMM tiling ----------------
#define BM 128
#define BN 128
#define BK 64                      // fp16 K elements per half-stage (4 k16 steps)
#define A_STG (BM * 128)           // 16384 B (128B rows, XOR-swizzled)
#define STG   (3 * A_STG)          // 49152 B : [Ahi | Alo | B] per half-stage
#define NSTG 2                     // two half-stages processed per barrier pair
#define GEMM_SMEM (NSTG * STG)     // 98304 B -> 2 CTAs/SM
#define CHUNKS 3072                // 16B chunks per half-stage: 1024 per buffer

// s is scaled by 1/SSCALE before the final GEMM to avoid fp16 overflow
#define SSCALE 64.0f

// ---------------- device scratch ----------------
__device__ __align__(256) __half g_wf [DIM*DIM];
__device__ __align__(256) __half g_wc [DIM*DIM];
__device__ __align__(256) __half g_wg [DIM*DIM];
__device__ __align__(256) __half g_wo [DIM*DIM];
__device__ __align__(256) __half g_wu [HID*DIM];
__device__ __align__(256) __half g_wg2[HID*DIM];
__device__ __align__(256) __half g_wout[DIM*HID];

__device__ __align__(256) __half g_xhi[BATCH*DIM], g_xlo[BATCH*DIM];
__device__ __align__(256) float g_F[BATCH*DIM], g_C[BATCH*DIM], g_G[BATCH*DIM];
__device__ __align__(256) __half g_thi[BATCH*DIM], g_tlo[BATCH*DIM];
__device__ __align__(256) float g_O[BATCH*DIM];
__device__ __align__(256) __half g_ohi[BATCH*DIM], g_olo[BATCH*DIM];
__device__ __align__(256) float g_GG[BATCH*HID], g_U[BATCH*HID];
__device__ __align__(256) __half g_sh[BATCH*HID];

// ---------------- PTX helpers ----------------
__device__ __forceinline__ uint32_t smem_u32(const void* p) {
    uint32_t a;
    asm("{ .reg .u64 t; cvta.to.shared.u64 t, %1; cvt.u32.u64 %0, t; }" : "=r"(a) : "l"(p));
    return a;
}
__device__ __forceinline__ void cp_async16(uint32_t s, const void* g) {
    asm volatile("cp.async.cg.shared.global [%0], [%1], 16;\n" :: "r"(s), "l"(g) : "memory");
}
__device__ __forceinline__ void cp_commit() {
    asm volatile("cp.async.commit_group;\n" ::: "memory");
}
__device__ __forceinline__ void ldsm_x4(uint32_t* r, uint32_t a) {
    asm volatile("ldmatrix.sync.aligned.m8n8.x4.shared.b16 {%0,%1,%2,%3}, [%4];\n"
                 : "=r"(r[0]), "=r"(r[1]), "=r"(r[2]), "=r"(r[3]) : "r"(a));
}
__device__ __forceinline__ void mma_f16(float* c, const uint32_t* a, const uint32_t* b) {
    asm volatile(
        "mma.sync.aligned.m16n8k16.row.col.f32.f16.f16.f32 "
        "{%0,%1,%2,%3}, {%4,%5,%6,%7}, {%8,%9}, {%0,%1,%2,%3};\n"
        : "+f"(c[0]), "+f"(c[1]), "+f"(c[2]), "+f"(c[3])
        : "r"(a[0]), "r"(a[1]), "r"(a[2]), "r"(a[3]), "r"(b[0]), "r"(b[1]));
}

// swizzled byte offset within a 128B-row buffer: row r, 16B chunk c
__device__ __forceinline__ uint32_t swz(int r, int c) {
    return (uint32_t)(r * 128 + ((c ^ (r & 7)) * 16));
}

__device__ __forceinline__ float sigmoidf_(float v) { return 1.0f / (1.0f + expf(-v)); }

// ---------------- elementwise ----------------
struct TernArgs {
    const float* src[7];
    __half*      dst[7];
};

__global__ void tern_all_kernel(TernArgs args) {
    const int ndd = DIM * DIM / 8;
    const int nhd = HID * DIM / 8;
    long i = (long)blockIdx.x * blockDim.x + threadIdx.x;
    long total = 4L * ndd + 3L * nhd;
    if (i >= total) return;
    int seg; long off;
    if (i < 4L * ndd) { seg = (int)(i / ndd); off = i - (long)seg * ndd; }
    else { long j = i - 4L * ndd; seg = 4 + (int)(j / nhd); off = j - (long)(seg - 4) * nhd; }
    const float4* s = (const float4*)args.src[seg];
    uint4* d = (uint4*)args.dst[seg];
    float4 a = s[2*off], b = s[2*off+1];
    float v[8] = {a.x, a.y, a.z, a.w, b.x, b.y, b.z, b.w};
    union { uint4 u; __half h[8]; } r;
    #pragma unroll
    for (int j = 0; j < 8; j++) {
        float t = (fabsf(v[j]) < 0.33f) ? 0.0f : (v[j] > 0.0f ? 1.0f : -1.0f);
        r.h[j] = __float2half_rn(t);
    }
    d[off] = r.u;
}

__global__ void split_kernel(const float4* __restrict__ v,
                             uint4* __restrict__ hi, uint4* __restrict__ lo, int n8) {
    int i = blockIdx.x * blockDim.x + threadIdx.x;
    if (i >= n8) return;
    float4 a = v[2*i], b = v[2*i+1];
    float x[8] = {a.x, a.y, a.z, a.w, b.x, b.y, b.z, b.w};
    union { uint4 u; __half h[8]; } rh, rl;
    #pragma unroll
    for (int j = 0; j < 8; j++) {
        __half h = __float2half_rn(x[j]);
        rh.h[j] = h;
        rl.h[j] = __float2half_rn(x[j] - __half2float(h));
    }
    hi[i] = rh.u; lo[i] = rl.u;
}

__global__ void mlgru_ew_kernel(int n4) {
    int i = blockIdx.x * blockDim.x + threadIdx.x;
    if (i >= n4) return;
    float4 f4 = ((const float4*)g_F)[i];
    float4 c4 = ((const float4*)g_C)[i];
    float4 g4 = ((const float4*)g_G)[i];
    float fv[4] = {f4.x, f4.y, f4.z, f4.w};
    float cv[4] = {c4.x, c4.y, c4.z, c4.w};
    float gv[4] = {g4.x, g4.y, g4.z, g4.w};
    union { uint2 u; __half h[4]; } rh, rl;
    #pragma unroll
    for (int j = 0; j < 4; j++) {
        float f = sigmoidf_(fv[j]);
        float c = cv[j] * sigmoidf_(cv[j]);
        float g = sigmoidf_(gv[j]);
        float t = g * (1.0f - f) * c;
        __half h = __float2half_rn(t);
        rh.h[j] = h;
        rl.h[j] = __float2half_rn(t - __half2float(h));
    }
    ((uint2*)g_thi)[i] = rh.u;
    ((uint2*)g_tlo)[i] = rl.u;
}

// s = sigmoid(GG)*silu(U) / SSCALE -> single fp16 (no lo: final GEMM is ungated)
__global__ void glu_ew_kernel(int n4) {
    int i = blockIdx.x * blockDim.x + threadIdx.x;
    if (i >= n4) return;
    float4 gg4 = ((const float4*)g_GG)[i];
    float4 u4  = ((const float4*)g_U)[i];
    float ggv[4] = {gg4.x, gg4.y, gg4.z, gg4.w};
    float uv[4]  = {u4.x, u4.y, u4.z, u4.w};
    union { uint2 u; __half h[4]; } rh;
    #pragma unroll
    for (int j = 0; j < 4; j++) {
        float gg = sigmoidf_(ggv[j]);
        float u  = uv[j] * sigmoidf_(uv[j]);
        rh.h[j] = __float2half_rn(gg * u * (1.0f / SSCALE));
    }
    ((uint2*)g_sh)[i] = rh.u;
}

// ---------------- HMMA GEMM (compile-time USELO) -----------------------------
// out[M,N] = alpha * ((Ahi [+ Alo])[M,K] @ W[N,K]^T) + bias   (fp32 out)
// CTA 128x128, 256 threads, warp tile 32x64, 2 CTAs/SM, XOR-swizzled smem.
// Two BK=64 half-stages per barrier pair (128 K-elems between barriers).
template <bool USELO>
__global__ __launch_bounds__(256, 2) void gemm_hmma(
    const __half* __restrict__ Ahi,
    const __half* __restrict__ Alo,
    const __half* __restrict__ W,
    const float* __restrict__ bias,
    float* __restrict__ out,
    int M, int N, int K, float alpha)
{
    extern __shared__ __align__(16) unsigned char smem[];

    const int tid  = threadIdx.x;
    const int lane = tid & 31;
    const int warp = tid >> 5;      // 0..7
    const int wm   = warp & 3;      // M band: 32 rows
    const int wn   = warp >> 2;     // N band: 64 cols
    const long bM  = (long)blockIdx.y * BM;
    const long bN  = (long)blockIdx.x * BN;

    const int KI = K / (2 * BK);    // iterations, 128 K-elems each

    float acc[2][8][4];
    #pragma unroll
    for (int i = 0; i < 2; i++)
        #pragma unroll
        for (int j = 0; j < 8; j++)
            #pragma unroll
            for (int k = 0; k < 4; k++) acc[i][j][k] = 0.0f;

    // fill one BK=64 half-stage (hs = 0 or 1) of iteration it_
    // CHUNKS = 3072: chunks [0,1024) Ahi, [1024,2048) Alo, [2048,3072) B.
    auto issue_half = [&](int it_, int hs) {
        long kk = (long)it_ * (2 * BK) + (long)hs * BK;
        unsigned char* s = smem + hs * STG;
        #pragma unroll
        for (int c = tid; c < CHUNKS; c += 256) {
            int buf = c >> 10;            // 0 Ahi, 1 Alo, 2 B
            if (!USELO && buf == 1) continue;
            int cc  = c & 1023;
            int row = cc >> 3, ch = cc & 7;
            const __half* g =
                (buf == 0) ? (Ahi + (bM + row) * (long)K + kk + ch * 8) :
                (buf == 1) ? (Alo + (bM + row) * (long)K + kk + ch * 8) :
                             (W   + (bN + row) * (long)K + kk + ch * 8);
            cp_async16(smem_u32(s + buf * A_STG + swz(row, ch)), g);
        }
        cp_commit();
    };

    issue_half(0, 0);
    issue_half(0, 1);

    const int g1 = (lane >> 3) & 1;
    const int g2 = lane >> 4;
    const int r8 = lane & 7;
    const int par = warp & 1;       // ks stagger

    for (int it = 0; it < KI; it++) {
        asm volatile("cp.async.wait_group 0;\n" ::: "memory");
        __syncthreads();

        #pragma unroll
        for (int hs = 0; hs < 2; hs++) {
            unsigned char* sAh = smem + hs * STG;
            unsigned char* sAl = sAh + A_STG;
            unsigned char* sB  = sAh + 2 * A_STG;

            #pragma unroll
            for (int ks = 0; ks < 4; ks++) {
                int kss = ks ^ par;
                uint32_t bF[8][2];
                #pragma unroll
                for (int nb = 0; nb < 4; nb++) {
                    int r = wn * 64 + nb * 16 + g2 * 8 + r8;
                    int c = kss * 2 + g1;
                    uint32_t t[4];
                    ldsm_x4(t, smem_u32(sB + swz(r, c)));
                    bF[nb * 2 + 0][0] = t[0]; bF[nb * 2 + 0][1] = t[1];
                    bF[nb * 2 + 1][0] = t[2]; bF[nb * 2 + 1][1] = t[3];
                }
                uint32_t aH[2][4];
                #pragma unroll
                for (int mi = 0; mi < 2; mi++) {
                    int r = wm * 32 + mi * 16 + g1 * 8 + r8;
                    int c = kss * 2 + g2;
                    ldsm_x4(aH[mi], smem_u32(sAh + swz(r, c)));
                }
                if (USELO) {
                    uint32_t aL[2][4];
                    #pragma unroll
                    for (int mi = 0; mi < 2; mi++) {
                        int r = wm * 32 + mi * 16 + g1 * 8 + r8;
                        int c = kss * 2 + g2;
                        ldsm_x4(aL[mi], smem_u32(sAl + swz(r, c)));
                    }
                    #pragma unroll
                    for (int mi = 0; mi < 2; mi++)
                        #pragma unroll
                        for (int nj = 0; nj < 8; nj++)
                            mma_f16(acc[mi][nj], aH[mi], bF[nj]);
                    #pragma unroll
                    for (int mi = 0; mi < 2; mi++)
                        #pragma unroll
                        for (int nj = 0; nj < 8; nj++)
                            mma_f16(acc[mi][nj], aL[mi], bF[nj]);
                } else {
                    #pragma unroll
                    for (int mi = 0; mi < 2; mi++)
                        #pragma unroll
                        for (int nj = 0; nj < 8; nj++)
                            mma_f16(acc[mi][nj], aH[mi], bF[nj]);
                }
            }
        }

        __syncthreads();
        if (it + 1 < KI) {
            issue_half(it + 1, 0);
            issue_half(it + 1, 1);
        }
    }

    // epilogue: alpha*acc + bias, fp32 store
    const int cg = lane >> 2, tg = lane & 3;
    #pragma unroll
    for (int mi = 0; mi < 2; mi++) {
        #pragma unroll
        for (int nj = 0; nj < 8; nj++) {
            long row = bM + wm * 32 + mi * 16 + cg;
            long col = bN + wn * 64 + nj * 8 + tg * 2;
            float b0 = bias[col], b1 = bias[col + 1];
            float2 v0 = make_float2(fmaf(alpha, acc[mi][nj][0], b0),
                                    fmaf(alpha, acc[mi][nj][1], b1));
            float2 v1 = make_float2(fmaf(alpha, acc[mi][nj][2], b0),
                                    fmaf(alpha, acc[mi][nj][3], b1));
            *reinterpret_cast<float2*>(out + row * (long)N + col)       = v0;
            *reinterpret_cast<float2*>(out + (row + 8) * (long)N + col) = v1;
        }
    }
}

// ---------------- host launcher ----------------
extern "C" void kernel_launch(void* const* d_in, const int* in_sizes, int n_in,
                              void* d_out, int out_size)
{
    (void)in_sizes; (void)n_in; (void)out_size;
    const float* x    = (const float*)d_in[0];
    const float* wf   = (const float*)d_in[1];
    const float* bf_  = (const float*)d_in[2];
    const float* wc   = (const float*)d_in[3];
    const float* bc   = (const float*)d_in[4];
    const float* wg   = (const float*)d_in[5];
    const float* bg   = (const float*)d_in[6];
    const float* wo   = (const float*)d_in[7];
    const float* bo   = (const float*)d_in[8];
    const float* wu   = (const float*)d_in[9];
    const float* bu   = (const float*)d_in[10];
    const float* wg2  = (const float*)d_in[11];
    const float* bg2  = (const float*)d_in[12];
    const float* wout = (const float*)d_in[13];
    const float* bout = (const float*)d_in[14];
    float* out = (float*)d_out;

    cudaFuncSetAttribute(gemm_hmma<true>,  cudaFuncAttributeMaxDynamicSharedMemorySize, GEMM_SMEM);
    cudaFuncSetAttribute(gemm_hmma<false>, cudaFuncAttributeMaxDynamicSharedMemorySize, GEMM_SMEM);

    void *p_wf, *p_wc, *p_wg, *p_wo, *p_wu, *p_wg2, *p_wout;
    void *p_xhi, *p_xlo, *p_F, *p_C, *p_G, *p_thi, *p_tlo;
    void *p_O, *p_ohi, *p_olo, *p_GG, *p_U, *p_sh;
    cudaGetSymbolAddress(&p_wf, g_wf);     cudaGetSymbolAddress(&p_wc, g_wc);
    cudaGetSymbolAddress(&p_wg, g_wg);     cudaGetSymbolAddress(&p_wo, g_wo);
    cudaGetSymbolAddress(&p_wu, g_wu);     cudaGetSymbolAddress(&p_wg2, g_wg2);
    cudaGetSymbolAddress(&p_wout, g_wout);
    cudaGetSymbolAddress(&p_xhi, g_xhi);   cudaGetSymbolAddress(&p_xlo, g_xlo);
    cudaGetSymbolAddress(&p_F, g_F);       cudaGetSymbolAddress(&p_C, g_C);
    cudaGetSymbolAddress(&p_G, g_G);
    cudaGetSymbolAddress(&p_thi, g_thi);   cudaGetSymbolAddress(&p_tlo, g_tlo);
    cudaGetSymbolAddress(&p_O, g_O);
    cudaGetSymbolAddress(&p_ohi, g_ohi);   cudaGetSymbolAddress(&p_olo, g_olo);
    cudaGetSymbolAddress(&p_GG, g_GG);     cudaGetSymbolAddress(&p_U, g_U);
    cudaGetSymbolAddress(&p_sh, g_sh);

    const int T = 256;
    const int nBD = BATCH * DIM, nBH = BATCH * HID;

    TernArgs ta;
    ta.src[0] = wf;   ta.dst[0] = (__half*)p_wf;
    ta.src[1] = wc;   ta.dst[1] = (__half*)p_wc;
    ta.src[2] = wg;   ta.dst[2] = (__half*)p_wg;
    ta.src[3] = wo;   ta.dst[3] = (__half*)p_wo;
    ta.src[4] = wu;   ta.dst[4] = (__half*)p_wu;
    ta.src[5] = wg2;  ta.dst[5] = (__half*)p_wg2;
    ta.src[6] = wout; ta.dst[6] = (__half*)p_wout;
    long tern_chunks = 4L * (DIM*DIM/8) + 3L * (HID*DIM/8);
    tern_all_kernel<<<(unsigned)((tern_chunks + T - 1) / T), T>>>(ta);

    split_kernel<<<(nBD/8 + T - 1)/T, T>>>((const float4*)x, (uint4*)p_xhi, (uint4*)p_xlo, nBD/8);

    dim3 gridD(DIM / BN, BATCH / BM);   // (16, 32)
    dim3 gridH(HID / BN, BATCH / BM);   // (64, 32)

    gemm_hmma<true><<<gridD, 256, GEMM_SMEM>>>((__half*)p_xhi, (__half*)p_xlo,
                                               (__half*)p_wf, bf_, (float*)p_F, BATCH, DIM, DIM, 1.0f);
    gemm_hmma<true><<<gridD, 256, GEMM_SMEM>>>((__half*)p_xhi, (__half*)p_xlo,
                                               (__half*)p_wc, bc,  (float*)p_C, BATCH, DIM, DIM, 1.0f);
    gemm_hmma<true><<<gridD, 256, GEMM_SMEM>>>((__half*)p_xhi, (__half*)p_xlo,
                                               (__half*)p_wg, bg,  (float*)p_G, BATCH, DIM, DIM, 1.0f);

    mlgru_ew_kernel<<<(nBD/4 + T - 1)/T, T>>>(nBD/4);

    gemm_hmma<true><<<gridD, 256, GEMM_SMEM>>>((__half*)p_thi, (__half*)p_tlo,
                                               (__half*)p_wo, bo, (float*)p_O, BATCH, DIM, DIM, 1.0f);
    split_kernel<<<(nBD/8 + T - 1)/T, T>>>((const float4*)p_O, (uint4*)p_ohi, (uint4*)p_olo, nBD/8);

    gemm_hmma<true><<<gridH, 256, GEMM_SMEM>>>((__half*)p_ohi, (__half*)p_olo,
                                               (__half*)p_wg2, bg2, (float*)p_GG, BATCH, HID, DIM, 1.0f);
    gemm_hmma<true><<<gridH, 256, GEMM_SMEM>>>((__half*)p_ohi, (__half*)p_olo,
                                               (__half*)p_wu,  bu,  (float*)p_U,  BATCH, HID, DIM, 1.0f);

    glu_ew_kernel<<<(nBH/4 + T - 1)/T, T>>>(nBH/4);

    // final GEMM: single fp16 A (no gate downstream -> no amplification)
    gemm_hmma<false><<<gridD, 256, GEMM_SMEM>>>((__half*)p_sh, (__half*)p_sh,
                                                (__half*)p_wout, bout, out, BATCH, DIM, HID, SSCALE);
}